// round 12
// baseline (speedup 1.0000x reference)
#include <cuda_runtime.h>
#include <cuda_fp16.h>
#include <cstdint>
#include <math.h>

// Problem constants
#define B_  4
#define S_  2048
#define D_  1024
#define H_  16
#define DK_ 64

// Scratch (device globals — no allocs)
__device__ int g_mflag[B_ * 8 * 32];
// pre-converted fp16 planes (packed pairs along k: one word = 2 fp16)
__device__ uint32_t g_Xpk[(size_t)3 * 8192 * 512];
__device__ uint32_t g_Wpk[(size_t)3 * 1024 * 512];
// projected Q/K/V, packed fp16 [bh][s][32 words]; Q pre-scaled by 0.125
__device__ uint32_t g_Qh[(size_t)64 * 2048 * 32];
__device__ uint32_t g_Kh[(size_t)64 * 2048 * 32];
__device__ uint32_t g_Vh[(size_t)64 * 2048 * 32];

// ---------------------------------------------------------------------------
// helpers
// ---------------------------------------------------------------------------
__device__ __forceinline__ uint32_t f16pk(float x0, float x1) {
    __half2 h = __floats2half2_rn(x0, x1);
    return *(uint32_t*)&h;
}

__device__ __forceinline__ void mma_fp16(float* d, const uint32_t* a,
                                         uint32_t b0, uint32_t b1)
{
    asm volatile(
        "mma.sync.aligned.m16n8k16.row.col.f32.f16.f16.f32 "
        "{%0,%1,%2,%3},{%4,%5,%6,%7},{%8,%9},{%0,%1,%2,%3};"
        : "+f"(d[0]), "+f"(d[1]), "+f"(d[2]), "+f"(d[3])
        : "r"(a[0]), "r"(a[1]), "r"(a[2]), "r"(a[3]), "r"(b0), "r"(b1));
}

__device__ __forceinline__ void cp_async16(uint32_t dst_smem, const void* src) {
    asm volatile("cp.async.cg.shared.global [%0], [%1], 16;"
                 :: "r"(dst_smem), "l"(src));
}

__device__ __forceinline__ void ldsm_x2(uint32_t& r0, uint32_t& r1, uint32_t addr) {
    asm volatile("ldmatrix.sync.aligned.m8n8.x2.shared.b16 {%0,%1}, [%2];"
                 : "=r"(r0), "=r"(r1) : "r"(addr));
}

__device__ __forceinline__ void ldsm_x4(uint32_t* r, uint32_t addr) {
    asm volatile("ldmatrix.sync.aligned.m8n8.x4.shared.b16 {%0,%1,%2,%3}, [%4];"
                 : "=r"(r[0]), "=r"(r[1]), "=r"(r[2]), "=r"(r[3]) : "r"(addr));
}

__device__ __forceinline__ void ldsm_x2_trans(uint32_t& r0, uint32_t& r1, uint32_t addr) {
    asm volatile("ldmatrix.sync.aligned.m8n8.x2.trans.shared.b16 {%0,%1}, [%2];"
                 : "=r"(r0), "=r"(r1) : "r"(addr));
}

// ---------------------------------------------------------------------------
// Prep: fp32 -> packed fp16 planes (unchanged, proven)
// ---------------------------------------------------------------------------
__global__ __launch_bounds__(256)
void prep_x(const float* __restrict__ q, const float* __restrict__ k,
            const float* __restrict__ v)
{
    const int z = blockIdx.z;
    const int m = blockIdx.x;
    const int kq = threadIdx.x;
    const float* src = (z == 0) ? q : (z == 1) ? k : v;
    float4 xv = *((const float4*)(src + (size_t)m * 1024) + kq);
    size_t w = ((size_t)z * 8192 + m) * 512 + kq * 2;
    *(uint2*)&g_Xpk[w] = make_uint2(f16pk(xv.x, xv.y), f16pk(xv.z, xv.w));
}

__global__ __launch_bounds__(256)
void prep_w(const float* __restrict__ wq, const float* __restrict__ wk,
            const float* __restrict__ wv)
{
    const int z = blockIdx.z;
    const int n = blockIdx.x;
    const int kq = threadIdx.x;
    const float* src = (z == 0) ? wq : (z == 1) ? wk : wv;
    float4 xv = *((const float4*)(src + (size_t)n * 1024) + kq);
    size_t w = ((size_t)z * 1024 + n) * 512 + kq * 2;
    *(uint2*)&g_Wpk[w] = make_uint2(f16pk(xv.x, xv.y), f16pk(xv.z, xv.w));
}

// ---------------------------------------------------------------------------
// Fused projection GEMM v2: fp16 m16n8k16, 4-stage cp.async pipeline (k32
// stages), ldmatrix fragment loads. CTA tile 128x128, 8 warps (2x4),
// warp tile 64x32. Accumulation order over k identical to v1 (bitwise same).
// smem per stage: A 128x20 + B 128x20 words (80B row stride); 4 stages.
// ---------------------------------------------------------------------------
#define PST 20
#define PLW (128 * PST)        // 2560 words per plane
#define STGW (2 * PLW)         // 5120 words per stage
#define NSTG 4

__global__ __launch_bounds__(256, 2)
void proj_gemm(const float* __restrict__ bq, const float* __restrict__ bk,
               const float* __restrict__ bv)
{
    extern __shared__ uint32_t sbuf[];   // NSTG * STGW words

    const int tid  = threadIdx.x;
    const int warp = tid >> 5;
    const int lane = tid & 31;
    const int grp  = lane >> 2;
    const int t4   = lane & 3;
    const int bm   = blockIdx.y;
    const int bn   = blockIdx.x;
    const int z    = blockIdx.z;
    const int wm   = (warp >> 2) * 64;
    const int wn   = (warp & 3) * 32;

    const float* bias = (z == 0) ? bq : (z == 1) ? bk : bv;
    uint32_t* outh    = (z == 0) ? g_Qh : (z == 1) ? g_Kh : g_Vh;
    const bool scale  = (z == 0);

    const uint32_t* xpk = g_Xpk + ((size_t)z * 8192 + bm * 128) * 512;
    const uint32_t* wpk = g_Wpk + ((size_t)z * 1024 + bn * 128) * 512;

    const uint32_t smb = (uint32_t)__cvta_generic_to_shared(sbuf);

    // issue one k32-tile into stage sel: A/B each 128 rows x 16 words
    const int ld_r  = tid >> 1;          // 0..127
    const int ld_c4 = (tid & 1) * 8;     // word offset 0 or 8 (two 16B chunks each)
    auto issue = [&](int kt, int sel) {
        uint32_t d0 = smb + (sel * STGW) * 4;
        const uint32_t* srcA = xpk + (size_t)ld_r * 512 + kt * 16 + ld_c4;
        const uint32_t* srcB = wpk + (size_t)ld_r * 512 + kt * 16 + ld_c4;
        uint32_t dA = d0 + (ld_r * PST + ld_c4) * 4;
        uint32_t dB = d0 + (PLW + ld_r * PST + ld_c4) * 4;
        cp_async16(dA, srcA);
        cp_async16(dA + 16, srcA + 4);
        cp_async16(dB, srcB);
        cp_async16(dB + 16, srcB + 4);
        asm volatile("cp.async.commit_group;");
    };

    float acc[4][4][4];
#pragma unroll
    for (int mf = 0; mf < 4; mf++)
#pragma unroll
        for (int nf = 0; nf < 4; nf++)
#pragma unroll
            for (int i = 0; i < 4; i++) acc[mf][nf][i] = 0.f;

    issue(0, 0);
    issue(1, 1);
    issue(2, 2);

    // per-lane ldmatrix address pieces (bytes), row stride 80
    const uint32_t lm_row = (lane & 15);
    const uint32_t lm_col = (lane >> 4) * 16;

    for (int ks = 0; ks < 32; ks++) {
        asm volatile("cp.async.wait_group 2;");   // stage ks resident
        __syncthreads();                          // all warps done with stage ks-1 too

        if (ks + 3 < 32) issue(ks + 3, (ks + 3) & 3);

        const uint32_t st = smb + ((ks & 3) * STGW) * 4;
        const uint32_t As = st;
        const uint32_t Bs = st + PLW * 4;

#pragma unroll
        for (int kc = 0; kc < 2; kc++) {
            uint32_t ah[4][4];
#pragma unroll
            for (int mf = 0; mf < 4; mf++)
                ldsm_x4(ah[mf], As + (wm + mf * 16 + lm_row) * 80 + lm_col + kc * 32);

#pragma unroll
            for (int pf = 0; pf < 2; pf++) {
                uint32_t bb[4];
                ldsm_x4(bb, Bs + (wn + pf * 16 + lm_row) * 80 + lm_col + kc * 32);
#pragma unroll
                for (int mf = 0; mf < 4; mf++) {
                    mma_fp16(acc[mf][pf * 2 + 0], ah[mf], bb[0], bb[2]);
                    mma_fp16(acc[mf][pf * 2 + 1], ah[mf], bb[1], bb[3]);
                }
            }
        }
    }

    // Epilogue: bias, optional scale, pack fp16, scatter into [bh][s][32 words]
#pragma unroll
    for (int mf = 0; mf < 4; mf++) {
        int row0 = bm * 128 + wm + mf * 16 + grp;
        int row1 = row0 + 8;
        int b0i = row0 >> 11, s0 = row0 & 2047;
        int b1i = row1 >> 11, s1 = row1 & 2047;
#pragma unroll
        for (int nf = 0; nf < 4; nf++) {
            int col = bn * 128 + wn + nf * 8 + 2 * t4;
            int h  = col >> 6;
            int wi = (col & 63) >> 1;
            float bb0 = bias[col], bb1 = bias[col + 1];
            float v00 = acc[mf][nf][0] + bb0;
            float v01 = acc[mf][nf][1] + bb1;
            float v10 = acc[mf][nf][2] + bb0;
            float v11 = acc[mf][nf][3] + bb1;
            if (scale) { v00 *= 0.125f; v01 *= 0.125f; v10 *= 0.125f; v11 *= 0.125f; }
            outh[((size_t)(b0i * 16 + h) * 2048 + s0) * 32 + wi] = f16pk(v00, v01);
            outh[((size_t)(b1i * 16 + h) * 2048 + s1) * 32 + wi] = f16pk(v10, v11);
        }
    }
}

// ---------------------------------------------------------------------------
// Mask scan — coalesced (round 11)
// ---------------------------------------------------------------------------
__global__ void mask_scan(const int* __restrict__ mask)
{
    const int kt = blockIdx.x;
    const int qt = blockIdx.y;
    const int b  = blockIdx.z;
    const int tr = threadIdx.x >> 4;
    const int tc = (threadIdx.x & 15) * 4;
    int ok = 1;
#pragma unroll
    for (int p = 0; p < 16; p++) {
        int row = p * 16 + tr;
        int4 v = *(const int4*)(mask + ((size_t)b * S_ + qt * 256 + row) * S_ + kt * 64 + tc);
        ok &= (v.x != 0) & (v.y != 0) & (v.z != 0) & (v.w != 0);
    }
    ok = __syncthreads_and(ok);
    if (threadIdx.x == 0) g_mflag[(b * 8 + qt) * 32 + kt] = ok;
}

// ---------------------------------------------------------------------------
// Flash attention (unchanged round-11 deferred-PV version, ~300us, at ~76%
// of the measured legacy-pipe MMA rate)
// ---------------------------------------------------------------------------
#define KVS 36
#define KVB (2 * 64 * KVS)

__global__ __launch_bounds__(512, 1)
void attn_mma(const int* __restrict__ mask, float* __restrict__ out)
{
    extern __shared__ uint32_t smu[];
    uint32_t* Pp = smu + 2 * KVB;

    const int tid  = threadIdx.x;
    const int warp = tid >> 5;
    const int lane = tid & 31;
    const int grp  = lane >> 2;
    const int t4   = lane & 3;

    const int qblk = blockIdx.x;
    const int bh   = blockIdx.y;
    const int b    = bh >> 4;
    const int h    = bh & 15;

    const uint32_t* Qh = g_Qh + ((size_t)bh * 2048 + qblk * 256) * 32;
    const uint32_t* Kh = g_Kh + (size_t)bh * 2048 * 32;
    const uint32_t* Vh = g_Vh + (size_t)bh * 2048 * 32;
    const int* maskg = mask + (size_t)b * S_ * S_ + (size_t)(qblk * 256) * S_;
    const int* mfl = g_mflag + (b * 8 + qblk) * 32;

    const int ra = warp * 16 + grp;
    const int rb = ra + 8;

    const uint32_t smb = (uint32_t)__cvta_generic_to_shared(smu);
    const uint32_t kb_l = (lane & 7) * (KVS * 4) + ((lane >> 3) & 1) * 16;
    const uint32_t vb_l = (lane & 15) * (KVS * 4);

    uint32_t qa[4][4];
#pragma unroll
    for (int kc = 0; kc < 4; kc++) {
        qa[kc][0] = Qh[(size_t)ra * 32 + kc * 8 + t4];
        qa[kc][1] = Qh[(size_t)rb * 32 + kc * 8 + t4];
        qa[kc][2] = Qh[(size_t)ra * 32 + kc * 8 + 4 + t4];
        qa[kc][3] = Qh[(size_t)rb * 32 + kc * 8 + 4 + t4];
    }

    float o[8][4];
#pragma unroll
    for (int nf = 0; nf < 8; nf++)
#pragma unroll
        for (int i = 0; i < 4; i++) o[nf][i] = 0.f;

    float m0 = -1e30f, m1 = -1e30f, l0 = 0.f, l1 = 0.f;
    float al0 = 1.f, al1 = 1.f;

    auto stage = [&](int t, int sel) {
        uint32_t* dst = smu + sel * KVB;
        int r = tid >> 3, c4 = (tid & 7) * 4;
        uint32_t dK = (uint32_t)__cvta_generic_to_shared(dst + r * KVS + c4);
        uint32_t dV = (uint32_t)__cvta_generic_to_shared(dst + 64 * KVS + r * KVS + c4);
        cp_async16(dK, Kh + (size_t)(t * 64 + r) * 32 + c4);
        cp_async16(dV, Vh + (size_t)(t * 64 + r) * 32 + c4);
        asm volatile("cp.async.commit_group;");
    };

    stage(0, 0);
    asm volatile("cp.async.wait_group 0;");
    __syncthreads();

    for (int t = 0; t < 32; t++) {
        const uint32_t Kt = smb + (t & 1) * (KVB * 4);

        float sc[8][4];
#pragma unroll
        for (int nf = 0; nf < 8; nf++) {
#pragma unroll
            for (int i = 0; i < 4; i++) sc[nf][i] = 0.f;
#pragma unroll
            for (int kc = 0; kc < 4; kc++) {
                uint32_t b0, b1;
                ldsm_x2(b0, b1, Kt + kb_l + nf * (8 * KVS * 4) + kc * 32);
                mma_fp16(sc[nf], qa[kc], b0, b1);
            }
        }

        if (t > 0) {
            const uint32_t Vp = smb + ((t - 1) & 1) * (KVB * 4) + 64 * KVS * 4;
#pragma unroll
            for (int nf = 0; nf < 8; nf++) {
                o[nf][0] *= al0; o[nf][1] *= al0;
                o[nf][2] *= al1; o[nf][3] *= al1;
            }
#pragma unroll
            for (int kc = 0; kc < 4; kc++) {
                uint32_t pa[4];
                pa[0] = Pp[ra * KVS + kc * 8 + t4];
                pa[1] = Pp[rb * KVS + kc * 8 + t4];
                pa[2] = Pp[ra * KVS + kc * 8 + 4 + t4];
                pa[3] = Pp[rb * KVS + kc * 8 + 4 + t4];
#pragma unroll
                for (int nf = 0; nf < 8; nf++) {
                    uint32_t b0, b1;
                    ldsm_x2_trans(b0, b1, Vp + vb_l + kc * (16 * KVS * 4) + nf * 16);
                    mma_fp16(o[nf], pa, b0, b1);
                }
            }
        }
        __syncthreads();

        if (t < 31) stage(t + 1, (t + 1) & 1);

        const int allones = mfl[t];
        if (!allones) {
#pragma unroll
            for (int nf = 0; nf < 8; nf++) {
                int kcol = t * 64 + nf * 8 + 2 * t4;
                int2 ma = *(const int2*)(maskg + (size_t)ra * S_ + kcol);
                int2 mb = *(const int2*)(maskg + (size_t)rb * S_ + kcol);
                if (ma.x == 0) sc[nf][0] = -1e9f;
                if (ma.y == 0) sc[nf][1] = -1e9f;
                if (mb.x == 0) sc[nf][2] = -1e9f;
                if (mb.y == 0) sc[nf][3] = -1e9f;
            }
        }
        float tma = -1e30f, tmb = -1e30f;
#pragma unroll
        for (int nf = 0; nf < 8; nf++) {
            tma = fmaxf(tma, fmaxf(sc[nf][0], sc[nf][1]));
            tmb = fmaxf(tmb, fmaxf(sc[nf][2], sc[nf][3]));
        }
        tma = fmaxf(tma, __shfl_xor_sync(0xffffffffu, tma, 1));
        tma = fmaxf(tma, __shfl_xor_sync(0xffffffffu, tma, 2));
        tmb = fmaxf(tmb, __shfl_xor_sync(0xffffffffu, tmb, 1));
        tmb = fmaxf(tmb, __shfl_xor_sync(0xffffffffu, tmb, 2));

        float mn0 = fmaxf(m0, tma);
        float mn1 = fmaxf(m1, tmb);
        al0 = __expf(m0 - mn0);
        al1 = __expf(m1 - mn1);
        m0 = mn0; m1 = mn1;

        float rs0 = 0.f, rs1 = 0.f;
#pragma unroll
        for (int nf = 0; nf < 8; nf++) {
            float p00 = __expf(sc[nf][0] - mn0);
            float p01 = __expf(sc[nf][1] - mn0);
            float p10 = __expf(sc[nf][2] - mn1);
            float p11 = __expf(sc[nf][3] - mn1);
            rs0 += p00 + p01;
            rs1 += p10 + p11;
            Pp[ra * KVS + nf * 4 + t4] = f16pk(p00, p01);
            Pp[rb * KVS + nf * 4 + t4] = f16pk(p10, p11);
        }
        rs0 += __shfl_xor_sync(0xffffffffu, rs0, 1);
        rs0 += __shfl_xor_sync(0xffffffffu, rs0, 2);
        rs1 += __shfl_xor_sync(0xffffffffu, rs1, 1);
        rs1 += __shfl_xor_sync(0xffffffffu, rs1, 2);
        l0 = l0 * al0 + rs0;
        l1 = l1 * al1 + rs1;

        if (t < 31) {
            asm volatile("cp.async.wait_group 0;");
            __syncthreads();
        }
    }

    __syncwarp();
    {
        const uint32_t Vp = smb + (31 & 1) * (KVB * 4) + 64 * KVS * 4;
#pragma unroll
        for (int nf = 0; nf < 8; nf++) {
            o[nf][0] *= al0; o[nf][1] *= al0;
            o[nf][2] *= al1; o[nf][3] *= al1;
        }
#pragma unroll
        for (int kc = 0; kc < 4; kc++) {
            uint32_t pa[4];
            pa[0] = Pp[ra * KVS + kc * 8 + t4];
            pa[1] = Pp[rb * KVS + kc * 8 + t4];
            pa[2] = Pp[ra * KVS + kc * 8 + 4 + t4];
            pa[3] = Pp[rb * KVS + kc * 8 + 4 + t4];
#pragma unroll
            for (int nf = 0; nf < 8; nf++) {
                uint32_t b0, b1;
                ldsm_x2_trans(b0, b1, Vp + vb_l + kc * (16 * KVS * 4) + nf * 16);
                mma_fp16(o[nf], pa, b0, b1);
            }
        }
    }

    float inv0 = 1.f / l0;
    float inv1 = 1.f / l1;
    int ga = qblk * 256 + ra;
    int gb = ga + 8;
    float* opa = out + ((size_t)b * S_ + ga) * D_ + h * 64;
    float* opb = out + ((size_t)b * S_ + gb) * D_ + h * 64;
#pragma unroll
    for (int nf = 0; nf < 8; nf++) {
        int cb = nf * 8 + 2 * t4;
        *(float2*)(opa + cb) = make_float2(o[nf][0] * inv0, o[nf][1] * inv0);
        *(float2*)(opb + cb) = make_float2(o[nf][2] * inv1, o[nf][3] * inv1);
    }
}

// ---------------------------------------------------------------------------
// Launch
// Inputs (metadata order): query, key, value, mask, Wq, bq, Wk, bk, Wv, bv
// ---------------------------------------------------------------------------
extern "C" void kernel_launch(void* const* d_in, const int* in_sizes, int n_in,
                              void* d_out, int out_size)
{
    const float* query = (const float*)d_in[0];
    const float* key   = (const float*)d_in[1];
    const float* value = (const float*)d_in[2];
    const int*   mask  = (const int*)  d_in[3];
    const float* Wq    = (const float*)d_in[4];
    const float* bq    = (const float*)d_in[5];
    const float* Wk    = (const float*)d_in[6];
    const float* bk    = (const float*)d_in[7];
    const float* Wv    = (const float*)d_in[8];
    const float* bv    = (const float*)d_in[9];
    float* out = (float*)d_out;

    // prep: fp32 -> packed fp16 planes
    prep_x<<<dim3(8192, 1, 3), 256>>>(query, key, value);
    prep_w<<<dim3(1024, 1, 3), 256>>>(Wq, Wk, Wv);
    mask_scan<<<dim3(32, 8, 4), 256>>>(mask);

    // fused projections (fp16, 4-stage pipeline, ldmatrix)
    const int psmem = NSTG * STGW * (int)sizeof(uint32_t);   // 81,920 B
    cudaFuncSetAttribute(proj_gemm, cudaFuncAttributeMaxDynamicSharedMemorySize, psmem);
    proj_gemm<<<dim3(8, 64, 3), 256, psmem>>>(bq, bk, bv);

    // attention (unchanged)
    const int asmem = (2 * KVB + 256 * KVS) * (int)sizeof(uint32_t);   // 73,728 B
    cudaFuncSetAttribute(attn_mma, cudaFuncAttributeMaxDynamicSharedMemorySize, asmem);
    attn_mma<<<dim3(8, 64), 512, asmem>>>(mask, out);
}

// round 13
// speedup vs baseline: 1.0939x; 1.0939x over previous
#include <cuda_runtime.h>
#include <cuda_fp16.h>
#include <cstdint>
#include <math.h>

// Problem constants
#define B_  4
#define S_  2048
#define D_  1024
#define H_  16
#define DK_ 64

// Scratch (device globals — no allocs)
__device__ int g_mflag[B_ * 8 * 32];
// pre-converted fp16 planes (packed pairs along k: one word = 2 fp16)
__device__ uint32_t g_Xpk[(size_t)3 * 8192 * 512];
__device__ uint32_t g_Wpk[(size_t)3 * 1024 * 512];
// projected Q/K/V, packed fp16 [bh][s][32 words]; Q pre-scaled by 0.125
__device__ uint32_t g_Qh[(size_t)64 * 2048 * 32];
__device__ uint32_t g_Kh[(size_t)64 * 2048 * 32];
__device__ uint32_t g_Vh[(size_t)64 * 2048 * 32];

// ---------------------------------------------------------------------------
// helpers
// ---------------------------------------------------------------------------
__device__ __forceinline__ uint32_t f16pk(float x0, float x1) {
    __half2 h = __floats2half2_rn(x0, x1);
    return *(uint32_t*)&h;
}

__device__ __forceinline__ void mma_fp16(float* d, const uint32_t* a,
                                         uint32_t b0, uint32_t b1)
{
    asm volatile(
        "mma.sync.aligned.m16n8k16.row.col.f32.f16.f16.f32 "
        "{%0,%1,%2,%3},{%4,%5,%6,%7},{%8,%9},{%0,%1,%2,%3};"
        : "+f"(d[0]), "+f"(d[1]), "+f"(d[2]), "+f"(d[3])
        : "r"(a[0]), "r"(a[1]), "r"(a[2]), "r"(a[3]), "r"(b0), "r"(b1));
}

__device__ __forceinline__ void cp_async16(uint32_t dst_smem, const void* src) {
    asm volatile("cp.async.cg.shared.global [%0], [%1], 16;"
                 :: "r"(dst_smem), "l"(src));
}

__device__ __forceinline__ void ldsm_x2(uint32_t& r0, uint32_t& r1, uint32_t addr) {
    asm volatile("ldmatrix.sync.aligned.m8n8.x2.shared.b16 {%0,%1}, [%2];"
                 : "=r"(r0), "=r"(r1) : "r"(addr));
}

__device__ __forceinline__ void ldsm_x2_trans(uint32_t& r0, uint32_t& r1, uint32_t addr) {
    asm volatile("ldmatrix.sync.aligned.m8n8.x2.trans.shared.b16 {%0,%1}, [%2];"
                 : "=r"(r0), "=r"(r1) : "r"(addr));
}

// ---------------------------------------------------------------------------
// Prep: fp32 -> packed fp16 planes (unchanged, proven)
// ---------------------------------------------------------------------------
__global__ __launch_bounds__(256)
void prep_x(const float* __restrict__ q, const float* __restrict__ k,
            const float* __restrict__ v)
{
    const int z = blockIdx.z;
    const int m = blockIdx.x;
    const int kq = threadIdx.x;
    const float* src = (z == 0) ? q : (z == 1) ? k : v;
    float4 xv = *((const float4*)(src + (size_t)m * 1024) + kq);
    size_t w = ((size_t)z * 8192 + m) * 512 + kq * 2;
    *(uint2*)&g_Xpk[w] = make_uint2(f16pk(xv.x, xv.y), f16pk(xv.z, xv.w));
}

__global__ __launch_bounds__(256)
void prep_w(const float* __restrict__ wq, const float* __restrict__ wk,
            const float* __restrict__ wv)
{
    const int z = blockIdx.z;
    const int n = blockIdx.x;
    const int kq = threadIdx.x;
    const float* src = (z == 0) ? wq : (z == 1) ? wk : wv;
    float4 xv = *((const float4*)(src + (size_t)n * 1024) + kq);
    size_t w = ((size_t)z * 1024 + n) * 512 + kq * 2;
    *(uint2*)&g_Wpk[w] = make_uint2(f16pk(xv.x, xv.y), f16pk(xv.z, xv.w));
}

// ---------------------------------------------------------------------------
// Fused projection GEMM (round-10 structure, proven): fp16 m16n8k16,
// k64 stages, scalar-LDS fragments (PST=36, conflict-free).
// CHANGE vs round 10: 3-stage pipeline, ONE barrier per k-step, issue after
// the barrier (prefetch distance ~1 full compute tile). MMA order unchanged.
// ---------------------------------------------------------------------------
#define PST 36
#define PLW (128 * PST)        // 4608 words per plane
#define STGW (2 * PLW)         // 9216 words per stage (A then B)
#define NSTG 3

__global__ __launch_bounds__(256, 2)
void proj_gemm(const float* __restrict__ bq, const float* __restrict__ bk,
               const float* __restrict__ bv)
{
    extern __shared__ uint32_t sbuf[];   // NSTG * STGW words

    const int tid  = threadIdx.x;
    const int warp = tid >> 5;
    const int lane = tid & 31;
    const int grp  = lane >> 2;
    const int t4   = lane & 3;
    const int bm   = blockIdx.y;
    const int bn   = blockIdx.x;
    const int z    = blockIdx.z;
    const int wm   = (warp >> 2) * 64;
    const int wn   = (warp & 3) * 32;

    const float* bias = (z == 0) ? bq : (z == 1) ? bk : bv;
    uint32_t* outh    = (z == 0) ? g_Qh : (z == 1) ? g_Kh : g_Vh;
    const bool scale  = (z == 0);

    const uint32_t* xpk = g_Xpk + ((size_t)z * 8192 + bm * 128) * 512;
    const uint32_t* wpk = g_Wpk + ((size_t)z * 1024 + bn * 128) * 512;

    // issue one k64-tile into stage sel (A/B each 128 rows x 32 words)
    auto issue = [&](int kt, int sel) {
        uint32_t* dst = sbuf + sel * STGW;
#pragma unroll
        for (int q = 0; q < 4; q++) {
            int idx = q * 256 + tid;
            int r = idx >> 3;
            int g4 = (idx & 7) * 4;
            uint32_t dA = (uint32_t)__cvta_generic_to_shared(dst + r * PST + g4);
            uint32_t dB = (uint32_t)__cvta_generic_to_shared(dst + PLW + r * PST + g4);
            cp_async16(dA, xpk + (size_t)r * 512 + kt * 32 + g4);
            cp_async16(dB, wpk + (size_t)r * 512 + kt * 32 + g4);
        }
        asm volatile("cp.async.commit_group;");
    };

    float acc[4][4][4];
#pragma unroll
    for (int mf = 0; mf < 4; mf++)
#pragma unroll
        for (int nf = 0; nf < 4; nf++)
#pragma unroll
            for (int i = 0; i < 4; i++) acc[mf][nf][i] = 0.f;

    issue(0, 0);
    issue(1, 1);

    int s_cur = 0;   // buffer holding stage ks
    int s_nxt = 2;   // buffer for stage ks+2
    for (int ks = 0; ks < 16; ks++) {
        asm volatile("cp.async.wait_group 1;");   // stage ks resident
        __syncthreads();                          // all warps done with buf[s_nxt]'s old stage

        if (ks + 2 < 16) issue(ks + 2, s_nxt);

        const uint32_t* sA = sbuf + s_cur * STGW;
        const uint32_t* sB = sA + PLW;

#pragma unroll
        for (int kc = 0; kc < 4; kc++) {
            const int kp = kc * 8 + t4;
            uint32_t ah[4][4];
#pragma unroll
            for (int mf = 0; mf < 4; mf++) {
                int r0 = wm + mf * 16 + grp;
                ah[mf][0] = sA[r0 * PST + kp];
                ah[mf][1] = sA[(r0 + 8) * PST + kp];
                ah[mf][2] = sA[r0 * PST + kp + 4];
                ah[mf][3] = sA[(r0 + 8) * PST + kp + 4];
            }
#pragma unroll
            for (int nf = 0; nf < 4; nf++) {
                int n = wn + nf * 8 + grp;
                uint32_t b0 = sB[n * PST + kp];
                uint32_t b1 = sB[n * PST + kp + 4];
#pragma unroll
                for (int mf = 0; mf < 4; mf++)
                    mma_fp16(acc[mf][nf], ah[mf], b0, b1);
            }
        }

        s_cur = (s_cur + 1 == NSTG) ? 0 : s_cur + 1;
        s_nxt = (s_nxt + 1 == NSTG) ? 0 : s_nxt + 1;
    }

    // Epilogue: bias, optional scale, pack fp16, scatter into [bh][s][32 words]
#pragma unroll
    for (int mf = 0; mf < 4; mf++) {
        int row0 = bm * 128 + wm + mf * 16 + grp;
        int row1 = row0 + 8;
        int b0i = row0 >> 11, s0 = row0 & 2047;
        int b1i = row1 >> 11, s1 = row1 & 2047;
#pragma unroll
        for (int nf = 0; nf < 4; nf++) {
            int col = bn * 128 + wn + nf * 8 + 2 * t4;
            int h  = col >> 6;
            int wi = (col & 63) >> 1;
            float bb0 = bias[col], bb1 = bias[col + 1];
            float v00 = acc[mf][nf][0] + bb0;
            float v01 = acc[mf][nf][1] + bb1;
            float v10 = acc[mf][nf][2] + bb0;
            float v11 = acc[mf][nf][3] + bb1;
            if (scale) { v00 *= 0.125f; v01 *= 0.125f; v10 *= 0.125f; v11 *= 0.125f; }
            outh[((size_t)(b0i * 16 + h) * 2048 + s0) * 32 + wi] = f16pk(v00, v01);
            outh[((size_t)(b1i * 16 + h) * 2048 + s1) * 32 + wi] = f16pk(v10, v11);
        }
    }
}

// ---------------------------------------------------------------------------
// Mask scan — coalesced (round 11, proven)
// ---------------------------------------------------------------------------
__global__ void mask_scan(const int* __restrict__ mask)
{
    const int kt = blockIdx.x;
    const int qt = blockIdx.y;
    const int b  = blockIdx.z;
    const int tr = threadIdx.x >> 4;
    const int tc = (threadIdx.x & 15) * 4;
    int ok = 1;
#pragma unroll
    for (int p = 0; p < 16; p++) {
        int row = p * 16 + tr;
        int4 v = *(const int4*)(mask + ((size_t)b * S_ + qt * 256 + row) * S_ + kt * 64 + tc);
        ok &= (v.x != 0) & (v.y != 0) & (v.z != 0) & (v.w != 0);
    }
    ok = __syncthreads_and(ok);
    if (threadIdx.x == 0) g_mflag[(b * 8 + qt) * 32 + kt] = ok;
}

// ---------------------------------------------------------------------------
// Flash attention (round-11 deferred-PV version, unchanged — ~300us, ~76%
// of measured legacy-pipe MMA rate)
// ---------------------------------------------------------------------------
#define KVS 36
#define KVB (2 * 64 * KVS)

__global__ __launch_bounds__(512, 1)
void attn_mma(const int* __restrict__ mask, float* __restrict__ out)
{
    extern __shared__ uint32_t smu[];
    uint32_t* Pp = smu + 2 * KVB;

    const int tid  = threadIdx.x;
    const int warp = tid >> 5;
    const int lane = tid & 31;
    const int grp  = lane >> 2;
    const int t4   = lane & 3;

    const int qblk = blockIdx.x;
    const int bh   = blockIdx.y;
    const int b    = bh >> 4;
    const int h    = bh & 15;

    const uint32_t* Qh = g_Qh + ((size_t)bh * 2048 + qblk * 256) * 32;
    const uint32_t* Kh = g_Kh + (size_t)bh * 2048 * 32;
    const uint32_t* Vh = g_Vh + (size_t)bh * 2048 * 32;
    const int* maskg = mask + (size_t)b * S_ * S_ + (size_t)(qblk * 256) * S_;
    const int* mfl = g_mflag + (b * 8 + qblk) * 32;

    const int ra = warp * 16 + grp;
    const int rb = ra + 8;

    const uint32_t smb = (uint32_t)__cvta_generic_to_shared(smu);
    const uint32_t kb_l = (lane & 7) * (KVS * 4) + ((lane >> 3) & 1) * 16;
    const uint32_t vb_l = (lane & 15) * (KVS * 4);

    uint32_t qa[4][4];
#pragma unroll
    for (int kc = 0; kc < 4; kc++) {
        qa[kc][0] = Qh[(size_t)ra * 32 + kc * 8 + t4];
        qa[kc][1] = Qh[(size_t)rb * 32 + kc * 8 + t4];
        qa[kc][2] = Qh[(size_t)ra * 32 + kc * 8 + 4 + t4];
        qa[kc][3] = Qh[(size_t)rb * 32 + kc * 8 + 4 + t4];
    }

    float o[8][4];
#pragma unroll
    for (int nf = 0; nf < 8; nf++)
#pragma unroll
        for (int i = 0; i < 4; i++) o[nf][i] = 0.f;

    float m0 = -1e30f, m1 = -1e30f, l0 = 0.f, l1 = 0.f;
    float al0 = 1.f, al1 = 1.f;

    auto stage = [&](int t, int sel) {
        uint32_t* dst = smu + sel * KVB;
        int r = tid >> 3, c4 = (tid & 7) * 4;
        uint32_t dK = (uint32_t)__cvta_generic_to_shared(dst + r * KVS + c4);
        uint32_t dV = (uint32_t)__cvta_generic_to_shared(dst + 64 * KVS + r * KVS + c4);
        cp_async16(dK, Kh + (size_t)(t * 64 + r) * 32 + c4);
        cp_async16(dV, Vh + (size_t)(t * 64 + r) * 32 + c4);
        asm volatile("cp.async.commit_group;");
    };

    stage(0, 0);
    asm volatile("cp.async.wait_group 0;");
    __syncthreads();

    for (int t = 0; t < 32; t++) {
        const uint32_t Kt = smb + (t & 1) * (KVB * 4);

        float sc[8][4];
#pragma unroll
        for (int nf = 0; nf < 8; nf++) {
#pragma unroll
            for (int i = 0; i < 4; i++) sc[nf][i] = 0.f;
#pragma unroll
            for (int kc = 0; kc < 4; kc++) {
                uint32_t b0, b1;
                ldsm_x2(b0, b1, Kt + kb_l + nf * (8 * KVS * 4) + kc * 32);
                mma_fp16(sc[nf], qa[kc], b0, b1);
            }
        }

        if (t > 0) {
            const uint32_t Vp = smb + ((t - 1) & 1) * (KVB * 4) + 64 * KVS * 4;
#pragma unroll
            for (int nf = 0; nf < 8; nf++) {
                o[nf][0] *= al0; o[nf][1] *= al0;
                o[nf][2] *= al1; o[nf][3] *= al1;
            }
#pragma unroll
            for (int kc = 0; kc < 4; kc++) {
                uint32_t pa[4];
                pa[0] = Pp[ra * KVS + kc * 8 + t4];
                pa[1] = Pp[rb * KVS + kc * 8 + t4];
                pa[2] = Pp[ra * KVS + kc * 8 + 4 + t4];
                pa[3] = Pp[rb * KVS + kc * 8 + 4 + t4];
#pragma unroll
                for (int nf = 0; nf < 8; nf++) {
                    uint32_t b0, b1;
                    ldsm_x2_trans(b0, b1, Vp + vb_l + kc * (16 * KVS * 4) + nf * 16);
                    mma_fp16(o[nf], pa, b0, b1);
                }
            }
        }
        __syncthreads();

        if (t < 31) stage(t + 1, (t + 1) & 1);

        const int allones = mfl[t];
        if (!allones) {
#pragma unroll
            for (int nf = 0; nf < 8; nf++) {
                int kcol = t * 64 + nf * 8 + 2 * t4;
                int2 ma = *(const int2*)(maskg + (size_t)ra * S_ + kcol);
                int2 mb = *(const int2*)(maskg + (size_t)rb * S_ + kcol);
                if (ma.x == 0) sc[nf][0] = -1e9f;
                if (ma.y == 0) sc[nf][1] = -1e9f;
                if (mb.x == 0) sc[nf][2] = -1e9f;
                if (mb.y == 0) sc[nf][3] = -1e9f;
            }
        }
        float tma = -1e30f, tmb = -1e30f;
#pragma unroll
        for (int nf = 0; nf < 8; nf++) {
            tma = fmaxf(tma, fmaxf(sc[nf][0], sc[nf][1]));
            tmb = fmaxf(tmb, fmaxf(sc[nf][2], sc[nf][3]));
        }
        tma = fmaxf(tma, __shfl_xor_sync(0xffffffffu, tma, 1));
        tma = fmaxf(tma, __shfl_xor_sync(0xffffffffu, tma, 2));
        tmb = fmaxf(tmb, __shfl_xor_sync(0xffffffffu, tmb, 1));
        tmb = fmaxf(tmb, __shfl_xor_sync(0xffffffffu, tmb, 2));

        float mn0 = fmaxf(m0, tma);
        float mn1 = fmaxf(m1, tmb);
        al0 = __expf(m0 - mn0);
        al1 = __expf(m1 - mn1);
        m0 = mn0; m1 = mn1;

        float rs0 = 0.f, rs1 = 0.f;
#pragma unroll
        for (int nf = 0; nf < 8; nf++) {
            float p00 = __expf(sc[nf][0] - mn0);
            float p01 = __expf(sc[nf][1] - mn0);
            float p10 = __expf(sc[nf][2] - mn1);
            float p11 = __expf(sc[nf][3] - mn1);
            rs0 += p00 + p01;
            rs1 += p10 + p11;
            Pp[ra * KVS + nf * 4 + t4] = f16pk(p00, p01);
            Pp[rb * KVS + nf * 4 + t4] = f16pk(p10, p11);
        }
        rs0 += __shfl_xor_sync(0xffffffffu, rs0, 1);
        rs0 += __shfl_xor_sync(0xffffffffu, rs0, 2);
        rs1 += __shfl_xor_sync(0xffffffffu, rs1, 1);
        rs1 += __shfl_xor_sync(0xffffffffu, rs1, 2);
        l0 = l0 * al0 + rs0;
        l1 = l1 * al1 + rs1;

        if (t < 31) {
            asm volatile("cp.async.wait_group 0;");
            __syncthreads();
        }
    }

    __syncwarp();
    {
        const uint32_t Vp = smb + (31 & 1) * (KVB * 4) + 64 * KVS * 4;
#pragma unroll
        for (int nf = 0; nf < 8; nf++) {
            o[nf][0] *= al0; o[nf][1] *= al0;
            o[nf][2] *= al1; o[nf][3] *= al1;
        }
#pragma unroll
        for (int kc = 0; kc < 4; kc++) {
            uint32_t pa[4];
            pa[0] = Pp[ra * KVS + kc * 8 + t4];
            pa[1] = Pp[rb * KVS + kc * 8 + t4];
            pa[2] = Pp[ra * KVS + kc * 8 + 4 + t4];
            pa[3] = Pp[rb * KVS + kc * 8 + 4 + t4];
#pragma unroll
            for (int nf = 0; nf < 8; nf++) {
                uint32_t b0, b1;
                ldsm_x2_trans(b0, b1, Vp + vb_l + kc * (16 * KVS * 4) + nf * 16);
                mma_fp16(o[nf], pa, b0, b1);
            }
        }
    }

    float inv0 = 1.f / l0;
    float inv1 = 1.f / l1;
    int ga = qblk * 256 + ra;
    int gb = ga + 8;
    float* opa = out + ((size_t)b * S_ + ga) * D_ + h * 64;
    float* opb = out + ((size_t)b * S_ + gb) * D_ + h * 64;
#pragma unroll
    for (int nf = 0; nf < 8; nf++) {
        int cb = nf * 8 + 2 * t4;
        *(float2*)(opa + cb) = make_float2(o[nf][0] * inv0, o[nf][1] * inv0);
        *(float2*)(opb + cb) = make_float2(o[nf][2] * inv1, o[nf][3] * inv1);
    }
}

// ---------------------------------------------------------------------------
// Launch
// Inputs (metadata order): query, key, value, mask, Wq, bq, Wk, bk, Wv, bv
// ---------------------------------------------------------------------------
extern "C" void kernel_launch(void* const* d_in, const int* in_sizes, int n_in,
                              void* d_out, int out_size)
{
    const float* query = (const float*)d_in[0];
    const float* key   = (const float*)d_in[1];
    const float* value = (const float*)d_in[2];
    const int*   mask  = (const int*)  d_in[3];
    const float* Wq    = (const float*)d_in[4];
    const float* bq    = (const float*)d_in[5];
    const float* Wk    = (const float*)d_in[6];
    const float* bk    = (const float*)d_in[7];
    const float* Wv    = (const float*)d_in[8];
    const float* bv    = (const float*)d_in[9];
    float* out = (float*)d_out;

    // prep: fp32 -> packed fp16 planes
    prep_x<<<dim3(8192, 1, 3), 256>>>(query, key, value);
    prep_w<<<dim3(1024, 1, 3), 256>>>(Wq, Wk, Wv);
    mask_scan<<<dim3(32, 8, 4), 256>>>(mask);

    // fused projections (fp16, 3-stage k64 pipeline, single barrier/step)
    const int psmem = NSTG * STGW * (int)sizeof(uint32_t);   // 110,592 B
    cudaFuncSetAttribute(proj_gemm, cudaFuncAttributeMaxDynamicSharedMemorySize, psmem);
    proj_gemm<<<dim3(8, 64, 3), 256, psmem>>>(bq, bk, bv);

    // attention (unchanged)
    const int asmem = (2 * KVB + 256 * KVS) * (int)sizeof(uint32_t);   // 73,728 B
    cudaFuncSetAttribute(attn_mma, cudaFuncAttributeMaxDynamicSharedMemorySize, asmem);
    attn_mma<<<dim3(8, 64), 512, asmem>>>(mask, out);
}

// round 14
// speedup vs baseline: 1.2131x; 1.1090x over previous
#include <cuda_runtime.h>
#include <cuda_fp16.h>
#include <cstdint>
#include <math.h>

// Problem constants
#define B_  4
#define S_  2048
#define D_  1024
#define H_  16
#define DK_ 64

// Scratch (device globals — no allocs)
__device__ int g_mflag[B_ * 8 * 32];
// pre-converted fp16 planes (packed pairs along k: one word = 2 fp16)
__device__ uint32_t g_Xpk[(size_t)3 * 8192 * 512];
__device__ uint32_t g_Wpk[(size_t)3 * 1024 * 512];
// projected Q/K/V, packed fp16 [bh][s][32 words]; Q pre-scaled by 0.125*log2(e)
__device__ uint32_t g_Qh[(size_t)64 * 2048 * 32];
__device__ uint32_t g_Kh[(size_t)64 * 2048 * 32];
__device__ uint32_t g_Vh[(size_t)64 * 2048 * 32];

// ---------------------------------------------------------------------------
// helpers
// ---------------------------------------------------------------------------
__device__ __forceinline__ uint32_t f16pk(float x0, float x1) {
    __half2 h = __floats2half2_rn(x0, x1);
    return *(uint32_t*)&h;
}

__device__ __forceinline__ float ex2(float x) {
    float r;
    asm("ex2.approx.f32 %0, %1;" : "=f"(r) : "f"(x));
    return r;
}

__device__ __forceinline__ void mma_fp16(float* d, const uint32_t* a,
                                         uint32_t b0, uint32_t b1)
{
    asm volatile(
        "mma.sync.aligned.m16n8k16.row.col.f32.f16.f16.f32 "
        "{%0,%1,%2,%3},{%4,%5,%6,%7},{%8,%9},{%0,%1,%2,%3};"
        : "+f"(d[0]), "+f"(d[1]), "+f"(d[2]), "+f"(d[3])
        : "r"(a[0]), "r"(a[1]), "r"(a[2]), "r"(a[3]), "r"(b0), "r"(b1));
}

__device__ __forceinline__ void cp_async16(uint32_t dst_smem, const void* src) {
    asm volatile("cp.async.cg.shared.global [%0], [%1], 16;"
                 :: "r"(dst_smem), "l"(src));
}

__device__ __forceinline__ void ldsm_x2(uint32_t& r0, uint32_t& r1, uint32_t addr) {
    asm volatile("ldmatrix.sync.aligned.m8n8.x2.shared.b16 {%0,%1}, [%2];"
                 : "=r"(r0), "=r"(r1) : "r"(addr));
}

__device__ __forceinline__ void ldsm_x2_trans(uint32_t& r0, uint32_t& r1, uint32_t addr) {
    asm volatile("ldmatrix.sync.aligned.m8n8.x2.trans.shared.b16 {%0,%1}, [%2];"
                 : "=r"(r0), "=r"(r1) : "r"(addr));
}

// ---------------------------------------------------------------------------
// Prep: fp32 -> packed fp16 planes (unchanged, proven)
// ---------------------------------------------------------------------------
__global__ __launch_bounds__(256)
void prep_x(const float* __restrict__ q, const float* __restrict__ k,
            const float* __restrict__ v)
{
    const int z = blockIdx.z;
    const int m = blockIdx.x;
    const int kq = threadIdx.x;
    const float* src = (z == 0) ? q : (z == 1) ? k : v;
    float4 xv = *((const float4*)(src + (size_t)m * 1024) + kq);
    size_t w = ((size_t)z * 8192 + m) * 512 + kq * 2;
    *(uint2*)&g_Xpk[w] = make_uint2(f16pk(xv.x, xv.y), f16pk(xv.z, xv.w));
}

__global__ __launch_bounds__(256)
void prep_w(const float* __restrict__ wq, const float* __restrict__ wk,
            const float* __restrict__ wv)
{
    const int z = blockIdx.z;
    const int n = blockIdx.x;
    const int kq = threadIdx.x;
    const float* src = (z == 0) ? wq : (z == 1) ? wk : wv;
    float4 xv = *((const float4*)(src + (size_t)n * 1024) + kq);
    size_t w = ((size_t)z * 1024 + n) * 512 + kq * 2;
    *(uint2*)&g_Wpk[w] = make_uint2(f16pk(xv.x, xv.y), f16pk(xv.z, xv.w));
}

// ---------------------------------------------------------------------------
// Fused projection GEMM (round-13 state, proven 178.7us).
// Q scale folded with log2(e): 0.125 * 1.44269504 so attention can use ex2.
// ---------------------------------------------------------------------------
#define PST 36
#define PLW (128 * PST)
#define STGW (2 * PLW)
#define NSTG 3
#define QSCALE 0.1803368801f   // 0.125 * log2(e)

__global__ __launch_bounds__(256, 2)
void proj_gemm(const float* __restrict__ bq, const float* __restrict__ bk,
               const float* __restrict__ bv)
{
    extern __shared__ uint32_t sbuf[];

    const int tid  = threadIdx.x;
    const int warp = tid >> 5;
    const int lane = tid & 31;
    const int grp  = lane >> 2;
    const int t4   = lane & 3;
    const int bm   = blockIdx.y;
    const int bn   = blockIdx.x;
    const int z    = blockIdx.z;
    const int wm   = (warp >> 2) * 64;
    const int wn   = (warp & 3) * 32;

    const float* bias = (z == 0) ? bq : (z == 1) ? bk : bv;
    uint32_t* outh    = (z == 0) ? g_Qh : (z == 1) ? g_Kh : g_Vh;
    const bool scale  = (z == 0);

    const uint32_t* xpk = g_Xpk + ((size_t)z * 8192 + bm * 128) * 512;
    const uint32_t* wpk = g_Wpk + ((size_t)z * 1024 + bn * 128) * 512;

    auto issue = [&](int kt, int sel) {
        uint32_t* dst = sbuf + sel * STGW;
#pragma unroll
        for (int q = 0; q < 4; q++) {
            int idx = q * 256 + tid;
            int r = idx >> 3;
            int g4 = (idx & 7) * 4;
            uint32_t dA = (uint32_t)__cvta_generic_to_shared(dst + r * PST + g4);
            uint32_t dB = (uint32_t)__cvta_generic_to_shared(dst + PLW + r * PST + g4);
            cp_async16(dA, xpk + (size_t)r * 512 + kt * 32 + g4);
            cp_async16(dB, wpk + (size_t)r * 512 + kt * 32 + g4);
        }
        asm volatile("cp.async.commit_group;");
    };

    float acc[4][4][4];
#pragma unroll
    for (int mf = 0; mf < 4; mf++)
#pragma unroll
        for (int nf = 0; nf < 4; nf++)
#pragma unroll
            for (int i = 0; i < 4; i++) acc[mf][nf][i] = 0.f;

    issue(0, 0);
    issue(1, 1);

    int s_cur = 0;
    int s_nxt = 2;
    for (int ks = 0; ks < 16; ks++) {
        asm volatile("cp.async.wait_group 1;");
        __syncthreads();

        if (ks + 2 < 16) issue(ks + 2, s_nxt);

        const uint32_t* sA = sbuf + s_cur * STGW;
        const uint32_t* sB = sA + PLW;

#pragma unroll
        for (int kc = 0; kc < 4; kc++) {
            const int kp = kc * 8 + t4;
            uint32_t ah[4][4];
#pragma unroll
            for (int mf = 0; mf < 4; mf++) {
                int r0 = wm + mf * 16 + grp;
                ah[mf][0] = sA[r0 * PST + kp];
                ah[mf][1] = sA[(r0 + 8) * PST + kp];
                ah[mf][2] = sA[r0 * PST + kp + 4];
                ah[mf][3] = sA[(r0 + 8) * PST + kp + 4];
            }
#pragma unroll
            for (int nf = 0; nf < 4; nf++) {
                int n = wn + nf * 8 + grp;
                uint32_t b0 = sB[n * PST + kp];
                uint32_t b1 = sB[n * PST + kp + 4];
#pragma unroll
                for (int mf = 0; mf < 4; mf++)
                    mma_fp16(acc[mf][nf], ah[mf], b0, b1);
            }
        }

        s_cur = (s_cur + 1 == NSTG) ? 0 : s_cur + 1;
        s_nxt = (s_nxt + 1 == NSTG) ? 0 : s_nxt + 1;
    }

#pragma unroll
    for (int mf = 0; mf < 4; mf++) {
        int row0 = bm * 128 + wm + mf * 16 + grp;
        int row1 = row0 + 8;
        int b0i = row0 >> 11, s0 = row0 & 2047;
        int b1i = row1 >> 11, s1 = row1 & 2047;
#pragma unroll
        for (int nf = 0; nf < 4; nf++) {
            int col = bn * 128 + wn + nf * 8 + 2 * t4;
            int h  = col >> 6;
            int wi = (col & 63) >> 1;
            float bb0 = bias[col], bb1 = bias[col + 1];
            float v00 = acc[mf][nf][0] + bb0;
            float v01 = acc[mf][nf][1] + bb1;
            float v10 = acc[mf][nf][2] + bb0;
            float v11 = acc[mf][nf][3] + bb1;
            if (scale) { v00 *= QSCALE; v01 *= QSCALE; v10 *= QSCALE; v11 *= QSCALE; }
            outh[((size_t)(b0i * 16 + h) * 2048 + s0) * 32 + wi] = f16pk(v00, v01);
            outh[((size_t)(b1i * 16 + h) * 2048 + s1) * 32 + wi] = f16pk(v10, v11);
        }
    }
}

// ---------------------------------------------------------------------------
// Mask scan — coalesced (proven)
// ---------------------------------------------------------------------------
__global__ void mask_scan(const int* __restrict__ mask)
{
    const int kt = blockIdx.x;
    const int qt = blockIdx.y;
    const int b  = blockIdx.z;
    const int tr = threadIdx.x >> 4;
    const int tc = (threadIdx.x & 15) * 4;
    int ok = 1;
#pragma unroll
    for (int p = 0; p < 16; p++) {
        int row = p * 16 + tr;
        int4 v = *(const int4*)(mask + ((size_t)b * S_ + qt * 256 + row) * S_ + kt * 64 + tc);
        ok &= (v.x != 0) & (v.y != 0) & (v.z != 0) & (v.w != 0);
    }
    ok = __syncthreads_and(ok);
    if (threadIdx.x == 0) g_mflag[(b * 8 + qt) * 32 + kt] = ok;
}

// ---------------------------------------------------------------------------
// Flash attention, FP16, deferred-PV, base-2 softmax.
// NEW: 256 threads (8 warps), 128-row q-tiles, 2 CTAs/SM — inter-CTA overlap
// keeps the tensor pipe fed while the other CTA runs softmax/barriers.
// smem: 2 KV buffers (18,432 B each) + P 128x36 words = 55,296 B per CTA.
// ---------------------------------------------------------------------------
#define KVS 36
#define KVB (2 * 64 * KVS)     // words per KV buffer (K then V)

__global__ __launch_bounds__(256, 2)
void attn_mma(const int* __restrict__ mask, float* __restrict__ out)
{
    extern __shared__ uint32_t smu[];
    uint32_t* Pp = smu + 2 * KVB;          // 128*36 words

    const int tid  = threadIdx.x;
    const int warp = tid >> 5;     // 0..7
    const int lane = tid & 31;
    const int grp  = lane >> 2;
    const int t4   = lane & 3;

    const int qblk = blockIdx.x;   // 0..15 (128-row q tiles)
    const int bh   = blockIdx.y;   // 0..63
    const int b    = bh >> 4;
    const int h    = bh & 15;

    const uint32_t* Qh = g_Qh + ((size_t)bh * 2048 + qblk * 128) * 32;
    const uint32_t* Kh = g_Kh + (size_t)bh * 2048 * 32;
    const uint32_t* Vh = g_Vh + (size_t)bh * 2048 * 32;
    const int* maskg = mask + (size_t)b * S_ * S_ + (size_t)(qblk * 128) * S_;
    const int* mfl = g_mflag + (b * 8 + (qblk >> 1)) * 32;

    const int ra = warp * 16 + grp;   // 0..127
    const int rb = ra + 8;

    const uint32_t smb = (uint32_t)__cvta_generic_to_shared(smu);
    const uint32_t kb_l = (lane & 7) * (KVS * 4) + ((lane >> 3) & 1) * 16;
    const uint32_t vb_l = (lane & 15) * (KVS * 4);

    // ---- Q fragments: direct LDG (one time) ----
    uint32_t qa[4][4];
#pragma unroll
    for (int kc = 0; kc < 4; kc++) {
        qa[kc][0] = Qh[(size_t)ra * 32 + kc * 8 + t4];
        qa[kc][1] = Qh[(size_t)rb * 32 + kc * 8 + t4];
        qa[kc][2] = Qh[(size_t)ra * 32 + kc * 8 + 4 + t4];
        qa[kc][3] = Qh[(size_t)rb * 32 + kc * 8 + 4 + t4];
    }

    float o[8][4];
#pragma unroll
    for (int nf = 0; nf < 8; nf++)
#pragma unroll
        for (int i = 0; i < 4; i++) o[nf][i] = 0.f;

    float m0 = -1e30f, m1 = -1e30f, l0 = 0.f, l1 = 0.f;
    float al0 = 1.f, al1 = 1.f;

    // stage K/V tile t (64 keys): 256 threads x 2 chunks each per plane
    auto stage = [&](int t, int sel) {
        uint32_t* dst = smu + sel * KVB;
#pragma unroll
        for (int p = 0; p < 2; p++) {
            int idx = p * 256 + tid;       // 0..511
            int r = idx >> 3;              // 0..63
            int c4 = (idx & 7) * 4;        // 0..28
            uint32_t dK = (uint32_t)__cvta_generic_to_shared(dst + r * KVS + c4);
            uint32_t dV = (uint32_t)__cvta_generic_to_shared(dst + 64 * KVS + r * KVS + c4);
            cp_async16(dK, Kh + (size_t)(t * 64 + r) * 32 + c4);
            cp_async16(dV, Vh + (size_t)(t * 64 + r) * 32 + c4);
        }
        asm volatile("cp.async.commit_group;");
    };

    stage(0, 0);
    asm volatile("cp.async.wait_group 0;");
    __syncthreads();

    for (int t = 0; t < 32; t++) {
        const uint32_t Kt = smb + (t & 1) * (KVB * 4);

        // ---- QK(t) ----
        float sc[8][4];
#pragma unroll
        for (int nf = 0; nf < 8; nf++) {
#pragma unroll
            for (int i = 0; i < 4; i++) sc[nf][i] = 0.f;
#pragma unroll
            for (int kc = 0; kc < 4; kc++) {
                uint32_t b0, b1;
                ldsm_x2(b0, b1, Kt + kb_l + nf * (8 * KVS * 4) + kc * 32);
                mma_fp16(sc[nf], qa[kc], b0, b1);
            }
        }

        // ---- PV(t-1) ----
        if (t > 0) {
            const uint32_t Vp = smb + ((t - 1) & 1) * (KVB * 4) + 64 * KVS * 4;
#pragma unroll
            for (int nf = 0; nf < 8; nf++) {
                o[nf][0] *= al0; o[nf][1] *= al0;
                o[nf][2] *= al1; o[nf][3] *= al1;
            }
#pragma unroll
            for (int kc = 0; kc < 4; kc++) {
                uint32_t pa[4];
                pa[0] = Pp[ra * KVS + kc * 8 + t4];
                pa[1] = Pp[rb * KVS + kc * 8 + t4];
                pa[2] = Pp[ra * KVS + kc * 8 + 4 + t4];
                pa[3] = Pp[rb * KVS + kc * 8 + 4 + t4];
#pragma unroll
                for (int nf = 0; nf < 8; nf++) {
                    uint32_t b0, b1;
                    ldsm_x2_trans(b0, b1, Vp + vb_l + kc * (16 * KVS * 4) + nf * 16);
                    mma_fp16(o[nf], pa, b0, b1);
                }
            }
        }
        __syncthreads();

        if (t < 31) stage(t + 1, (t + 1) & 1);

        // ---- softmax(t), base-2 domain ----
        const int allones = mfl[t];
        if (!allones) {
#pragma unroll
            for (int nf = 0; nf < 8; nf++) {
                int kcol = t * 64 + nf * 8 + 2 * t4;
                int2 ma = *(const int2*)(maskg + (size_t)ra * S_ + kcol);
                int2 mb = *(const int2*)(maskg + (size_t)rb * S_ + kcol);
                if (ma.x == 0) sc[nf][0] = -1e9f;
                if (ma.y == 0) sc[nf][1] = -1e9f;
                if (mb.x == 0) sc[nf][2] = -1e9f;
                if (mb.y == 0) sc[nf][3] = -1e9f;
            }
        }
        float tma = -1e30f, tmb = -1e30f;
#pragma unroll
        for (int nf = 0; nf < 8; nf++) {
            tma = fmaxf(tma, fmaxf(sc[nf][0], sc[nf][1]));
            tmb = fmaxf(tmb, fmaxf(sc[nf][2], sc[nf][3]));
        }
        tma = fmaxf(tma, __shfl_xor_sync(0xffffffffu, tma, 1));
        tma = fmaxf(tma, __shfl_xor_sync(0xffffffffu, tma, 2));
        tmb = fmaxf(tmb, __shfl_xor_sync(0xffffffffu, tmb, 1));
        tmb = fmaxf(tmb, __shfl_xor_sync(0xffffffffu, tmb, 2));

        float mn0 = fmaxf(m0, tma);
        float mn1 = fmaxf(m1, tmb);
        al0 = ex2(m0 - mn0);
        al1 = ex2(m1 - mn1);
        m0 = mn0; m1 = mn1;

        float rs0 = 0.f, rs1 = 0.f;
#pragma unroll
        for (int nf = 0; nf < 8; nf++) {
            float p00 = ex2(sc[nf][0] - mn0);
            float p01 = ex2(sc[nf][1] - mn0);
            float p10 = ex2(sc[nf][2] - mn1);
            float p11 = ex2(sc[nf][3] - mn1);
            rs0 += p00 + p01;
            rs1 += p10 + p11;
            Pp[ra * KVS + nf * 4 + t4] = f16pk(p00, p01);
            Pp[rb * KVS + nf * 4 + t4] = f16pk(p10, p11);
        }
        rs0 += __shfl_xor_sync(0xffffffffu, rs0, 1);
        rs0 += __shfl_xor_sync(0xffffffffu, rs0, 2);
        rs1 += __shfl_xor_sync(0xffffffffu, rs1, 1);
        rs1 += __shfl_xor_sync(0xffffffffu, rs1, 2);
        l0 = l0 * al0 + rs0;
        l1 = l1 * al1 + rs1;

        if (t < 31) {
            asm volatile("cp.async.wait_group 0;");
            __syncthreads();
        }
    }

    // ---- final PV(31) ----
    __syncwarp();
    {
        const uint32_t Vp = smb + (31 & 1) * (KVB * 4) + 64 * KVS * 4;
#pragma unroll
        for (int nf = 0; nf < 8; nf++) {
            o[nf][0] *= al0; o[nf][1] *= al0;
            o[nf][2] *= al1; o[nf][3] *= al1;
        }
#pragma unroll
        for (int kc = 0; kc < 4; kc++) {
            uint32_t pa[4];
            pa[0] = Pp[ra * KVS + kc * 8 + t4];
            pa[1] = Pp[rb * KVS + kc * 8 + t4];
            pa[2] = Pp[ra * KVS + kc * 8 + 4 + t4];
            pa[3] = Pp[rb * KVS + kc * 8 + 4 + t4];
#pragma unroll
            for (int nf = 0; nf < 8; nf++) {
                uint32_t b0, b1;
                ldsm_x2_trans(b0, b1, Vp + vb_l + kc * (16 * KVS * 4) + nf * 16);
                mma_fp16(o[nf], pa, b0, b1);
            }
        }
    }

    // ---- finalize: O / l, write [B,S,D] ----
    float inv0 = 1.f / l0;
    float inv1 = 1.f / l1;
    int ga = qblk * 128 + ra;
    int gb = ga + 8;
    float* opa = out + ((size_t)b * S_ + ga) * D_ + h * 64;
    float* opb = out + ((size_t)b * S_ + gb) * D_ + h * 64;
#pragma unroll
    for (int nf = 0; nf < 8; nf++) {
        int cb = nf * 8 + 2 * t4;
        *(float2*)(opa + cb) = make_float2(o[nf][0] * inv0, o[nf][1] * inv0);
        *(float2*)(opb + cb) = make_float2(o[nf][2] * inv1, o[nf][3] * inv1);
    }
}

// ---------------------------------------------------------------------------
// Launch
// Inputs (metadata order): query, key, value, mask, Wq, bq, Wk, bk, Wv, bv
// ---------------------------------------------------------------------------
extern "C" void kernel_launch(void* const* d_in, const int* in_sizes, int n_in,
                              void* d_out, int out_size)
{
    const float* query = (const float*)d_in[0];
    const float* key   = (const float*)d_in[1];
    const float* value = (const float*)d_in[2];
    const int*   mask  = (const int*)  d_in[3];
    const float* Wq    = (const float*)d_in[4];
    const float* bq    = (const float*)d_in[5];
    const float* Wk    = (const float*)d_in[6];
    const float* bk    = (const float*)d_in[7];
    const float* Wv    = (const float*)d_in[8];
    const float* bv    = (const float*)d_in[9];
    float* out = (float*)d_out;

    // prep: fp32 -> packed fp16 planes
    prep_x<<<dim3(8192, 1, 3), 256>>>(query, key, value);
    prep_w<<<dim3(1024, 1, 3), 256>>>(Wq, Wk, Wv);
    mask_scan<<<dim3(32, 8, 4), 256>>>(mask);

    // fused projections (fp16, 3-stage k64 pipeline)
    const int psmem = NSTG * STGW * (int)sizeof(uint32_t);   // 110,592 B
    cudaFuncSetAttribute(proj_gemm, cudaFuncAttributeMaxDynamicSharedMemorySize, psmem);
    proj_gemm<<<dim3(8, 64, 3), 256, psmem>>>(bq, bk, bv);

    // attention: 256 threads, 128-row q tiles, 2 CTAs/SM
    const int asmem = (2 * KVB + 128 * KVS) * (int)sizeof(uint32_t);   // 55,296 B
    cudaFuncSetAttribute(attn_mma, cudaFuncAttributeMaxDynamicSharedMemorySize, asmem);
    attn_mma<<<dim3(16, 64), 256, asmem>>>(mask, out);
}

// round 15
// speedup vs baseline: 1.2507x; 1.0310x over previous
#include <cuda_runtime.h>
#include <cuda_fp16.h>
#include <cstdint>
#include <math.h>

// Problem constants
#define B_  4
#define S_  2048
#define D_  1024
#define H_  16
#define DK_ 64

// Scratch (device globals — no allocs)
__device__ int g_mflag[B_ * 8 * 32];
// pre-converted fp16 planes (packed pairs along k: one word = 2 fp16)
__device__ uint32_t g_Xpk[(size_t)3 * 8192 * 512];
__device__ uint32_t g_Wpk[(size_t)3 * 1024 * 512];
// projected Q/K/V, packed fp16 [bh][s][32 words]; Q pre-scaled by 0.125*log2(e)
__device__ uint32_t g_Qh[(size_t)64 * 2048 * 32];
__device__ uint32_t g_Kh[(size_t)64 * 2048 * 32];
__device__ uint32_t g_Vh[(size_t)64 * 2048 * 32];

// ---------------------------------------------------------------------------
// helpers
// ---------------------------------------------------------------------------
__device__ __forceinline__ uint32_t f16pk(float x0, float x1) {
    __half2 h = __floats2half2_rn(x0, x1);
    return *(uint32_t*)&h;
}

__device__ __forceinline__ float ex2(float x) {
    float r;
    asm("ex2.approx.f32 %0, %1;" : "=f"(r) : "f"(x));
    return r;
}

__device__ __forceinline__ void mma_fp16(float* d, const uint32_t* a,
                                         uint32_t b0, uint32_t b1)
{
    asm volatile(
        "mma.sync.aligned.m16n8k16.row.col.f32.f16.f16.f32 "
        "{%0,%1,%2,%3},{%4,%5,%6,%7},{%8,%9},{%0,%1,%2,%3};"
        : "+f"(d[0]), "+f"(d[1]), "+f"(d[2]), "+f"(d[3])
        : "r"(a[0]), "r"(a[1]), "r"(a[2]), "r"(a[3]), "r"(b0), "r"(b1));
}

__device__ __forceinline__ void cp_async16(uint32_t dst_smem, const void* src) {
    asm volatile("cp.async.cg.shared.global [%0], [%1], 16;"
                 :: "r"(dst_smem), "l"(src));
}

__device__ __forceinline__ void ldsm_x2(uint32_t& r0, uint32_t& r1, uint32_t addr) {
    asm volatile("ldmatrix.sync.aligned.m8n8.x2.shared.b16 {%0,%1}, [%2];"
                 : "=r"(r0), "=r"(r1) : "r"(addr));
}

__device__ __forceinline__ void ldsm_x2_trans(uint32_t& r0, uint32_t& r1, uint32_t addr) {
    asm volatile("ldmatrix.sync.aligned.m8n8.x2.trans.shared.b16 {%0,%1}, [%2];"
                 : "=r"(r0), "=r"(r1) : "r"(addr));
}

// ---------------------------------------------------------------------------
// Prep: fp32 -> packed fp16 planes. Merged X+W in one launch:
// blockIdx.x < 8192 -> X row; else W row (x - 8192).
// ---------------------------------------------------------------------------
__global__ __launch_bounds__(256)
void prep_xw(const float* __restrict__ q, const float* __restrict__ k,
             const float* __restrict__ v,
             const float* __restrict__ wq, const float* __restrict__ wk,
             const float* __restrict__ wv)
{
    const int z = blockIdx.z;
    const int x = blockIdx.x;
    const int kq = threadIdx.x;
    if (x < 8192) {
        const float* src = (z == 0) ? q : (z == 1) ? k : v;
        float4 xv = *((const float4*)(src + (size_t)x * 1024) + kq);
        size_t w = ((size_t)z * 8192 + x) * 512 + kq * 2;
        *(uint2*)&g_Xpk[w] = make_uint2(f16pk(xv.x, xv.y), f16pk(xv.z, xv.w));
    } else {
        const int n = x - 8192;   // 0..1023
        const float* src = (z == 0) ? wq : (z == 1) ? wk : wv;
        float4 xv = *((const float4*)(src + (size_t)n * 1024) + kq);
        size_t w = ((size_t)z * 1024 + n) * 512 + kq * 2;
        *(uint2*)&g_Wpk[w] = make_uint2(f16pk(xv.x, xv.y), f16pk(xv.z, xv.w));
    }
}

// ---------------------------------------------------------------------------
// Fused projection GEMM (round-13 state, proven ~179us).
// Q scale folded with log2(e) so attention uses ex2.
// ---------------------------------------------------------------------------
#define PST 36
#define PLW (128 * PST)
#define STGW (2 * PLW)
#define NSTG 3
#define QSCALE 0.1803368801f   // 0.125 * log2(e)

__global__ __launch_bounds__(256, 2)
void proj_gemm(const float* __restrict__ bq, const float* __restrict__ bk,
               const float* __restrict__ bv)
{
    extern __shared__ uint32_t sbuf[];

    const int tid  = threadIdx.x;
    const int warp = tid >> 5;
    const int lane = tid & 31;
    const int grp  = lane >> 2;
    const int t4   = lane & 3;
    const int bm   = blockIdx.y;
    const int bn   = blockIdx.x;
    const int z    = blockIdx.z;
    const int wm   = (warp >> 2) * 64;
    const int wn   = (warp & 3) * 32;

    const float* bias = (z == 0) ? bq : (z == 1) ? bk : bv;
    uint32_t* outh    = (z == 0) ? g_Qh : (z == 1) ? g_Kh : g_Vh;
    const bool scale  = (z == 0);

    const uint32_t* xpk = g_Xpk + ((size_t)z * 8192 + bm * 128) * 512;
    const uint32_t* wpk = g_Wpk + ((size_t)z * 1024 + bn * 128) * 512;

    auto issue = [&](int kt, int sel) {
        uint32_t* dst = sbuf + sel * STGW;
#pragma unroll
        for (int q = 0; q < 4; q++) {
            int idx = q * 256 + tid;
            int r = idx >> 3;
            int g4 = (idx & 7) * 4;
            uint32_t dA = (uint32_t)__cvta_generic_to_shared(dst + r * PST + g4);
            uint32_t dB = (uint32_t)__cvta_generic_to_shared(dst + PLW + r * PST + g4);
            cp_async16(dA, xpk + (size_t)r * 512 + kt * 32 + g4);
            cp_async16(dB, wpk + (size_t)r * 512 + kt * 32 + g4);
        }
        asm volatile("cp.async.commit_group;");
    };

    float acc[4][4][4];
#pragma unroll
    for (int mf = 0; mf < 4; mf++)
#pragma unroll
        for (int nf = 0; nf < 4; nf++)
#pragma unroll
            for (int i = 0; i < 4; i++) acc[mf][nf][i] = 0.f;

    issue(0, 0);
    issue(1, 1);

    int s_cur = 0;
    int s_nxt = 2;
    for (int ks = 0; ks < 16; ks++) {
        asm volatile("cp.async.wait_group 1;");
        __syncthreads();

        if (ks + 2 < 16) issue(ks + 2, s_nxt);

        const uint32_t* sA = sbuf + s_cur * STGW;
        const uint32_t* sB = sA + PLW;

#pragma unroll
        for (int kc = 0; kc < 4; kc++) {
            const int kp = kc * 8 + t4;
            uint32_t ah[4][4];
#pragma unroll
            for (int mf = 0; mf < 4; mf++) {
                int r0 = wm + mf * 16 + grp;
                ah[mf][0] = sA[r0 * PST + kp];
                ah[mf][1] = sA[(r0 + 8) * PST + kp];
                ah[mf][2] = sA[r0 * PST + kp + 4];
                ah[mf][3] = sA[(r0 + 8) * PST + kp + 4];
            }
#pragma unroll
            for (int nf = 0; nf < 4; nf++) {
                int n = wn + nf * 8 + grp;
                uint32_t b0 = sB[n * PST + kp];
                uint32_t b1 = sB[n * PST + kp + 4];
#pragma unroll
                for (int mf = 0; mf < 4; mf++)
                    mma_fp16(acc[mf][nf], ah[mf], b0, b1);
            }
        }

        s_cur = (s_cur + 1 == NSTG) ? 0 : s_cur + 1;
        s_nxt = (s_nxt + 1 == NSTG) ? 0 : s_nxt + 1;
    }

#pragma unroll
    for (int mf = 0; mf < 4; mf++) {
        int row0 = bm * 128 + wm + mf * 16 + grp;
        int row1 = row0 + 8;
        int b0i = row0 >> 11, s0 = row0 & 2047;
        int b1i = row1 >> 11, s1 = row1 & 2047;
#pragma unroll
        for (int nf = 0; nf < 4; nf++) {
            int col = bn * 128 + wn + nf * 8 + 2 * t4;
            int h  = col >> 6;
            int wi = (col & 63) >> 1;
            float bb0 = bias[col], bb1 = bias[col + 1];
            float v00 = acc[mf][nf][0] + bb0;
            float v01 = acc[mf][nf][1] + bb1;
            float v10 = acc[mf][nf][2] + bb0;
            float v11 = acc[mf][nf][3] + bb1;
            if (scale) { v00 *= QSCALE; v01 *= QSCALE; v10 *= QSCALE; v11 *= QSCALE; }
            outh[((size_t)(b0i * 16 + h) * 2048 + s0) * 32 + wi] = f16pk(v00, v01);
            outh[((size_t)(b1i * 16 + h) * 2048 + s1) * 32 + wi] = f16pk(v10, v11);
        }
    }
}

// ---------------------------------------------------------------------------
// Mask scan — coalesced (proven)
// ---------------------------------------------------------------------------
__global__ void mask_scan(const int* __restrict__ mask)
{
    const int kt = blockIdx.x;
    const int qt = blockIdx.y;
    const int b  = blockIdx.z;
    const int tr = threadIdx.x >> 4;
    const int tc = (threadIdx.x & 15) * 4;
    int ok = 1;
#pragma unroll
    for (int p = 0; p < 16; p++) {
        int row = p * 16 + tr;
        int4 v = *(const int4*)(mask + ((size_t)b * S_ + qt * 256 + row) * S_ + kt * 64 + tc);
        ok &= (v.x != 0) & (v.y != 0) & (v.z != 0) & (v.w != 0);
    }
    ok = __syncthreads_and(ok);
    if (threadIdx.x == 0) g_mflag[(b * 8 + qt) * 32 + kt] = ok;
}

// ---------------------------------------------------------------------------
// Flash attention, FP16, deferred-PV, base-2 softmax.
// Round 15: 128 threads (4 warps), 64-row q-tiles, 4 CTAs/SM — four
// independent barrier domains per SM keep the tensor pipe fed.
// smem: 2 KV buffers + P 64x36 words = 46,080 B per CTA.
// ---------------------------------------------------------------------------
#define KVS 36
#define KVB (2 * 64 * KVS)     // words per KV buffer (K then V)

__global__ __launch_bounds__(128, 4)
void attn_mma(const int* __restrict__ mask, float* __restrict__ out)
{
    extern __shared__ uint32_t smu[];
    uint32_t* Pp = smu + 2 * KVB;          // 64*36 words

    const int tid  = threadIdx.x;
    const int warp = tid >> 5;     // 0..3
    const int lane = tid & 31;
    const int grp  = lane >> 2;
    const int t4   = lane & 3;

    const int qblk = blockIdx.x;   // 0..31 (64-row q tiles)
    const int bh   = blockIdx.y;   // 0..63
    const int b    = bh >> 4;
    const int h    = bh & 15;

    const uint32_t* Qh = g_Qh + ((size_t)bh * 2048 + qblk * 64) * 32;
    const uint32_t* Kh = g_Kh + (size_t)bh * 2048 * 32;
    const uint32_t* Vh = g_Vh + (size_t)bh * 2048 * 32;
    const int* maskg = mask + (size_t)b * S_ * S_ + (size_t)(qblk * 64) * S_;
    const int* mfl = g_mflag + (b * 8 + (qblk >> 2)) * 32;

    const int ra = warp * 16 + grp;   // 0..63
    const int rb = ra + 8;

    const uint32_t smb = (uint32_t)__cvta_generic_to_shared(smu);
    const uint32_t kb_l = (lane & 7) * (KVS * 4) + ((lane >> 3) & 1) * 16;
    const uint32_t vb_l = (lane & 15) * (KVS * 4);

    // ---- Q fragments: direct LDG (one time) ----
    uint32_t qa[4][4];
#pragma unroll
    for (int kc = 0; kc < 4; kc++) {
        qa[kc][0] = Qh[(size_t)ra * 32 + kc * 8 + t4];
        qa[kc][1] = Qh[(size_t)rb * 32 + kc * 8 + t4];
        qa[kc][2] = Qh[(size_t)ra * 32 + kc * 8 + 4 + t4];
        qa[kc][3] = Qh[(size_t)rb * 32 + kc * 8 + 4 + t4];
    }

    float o[8][4];
#pragma unroll
    for (int nf = 0; nf < 8; nf++)
#pragma unroll
        for (int i = 0; i < 4; i++) o[nf][i] = 0.f;

    float m0 = -1e30f, m1 = -1e30f, l0 = 0.f, l1 = 0.f;
    float al0 = 1.f, al1 = 1.f;

    // stage K/V tile t (64 keys): 128 threads x 4 chunks each per plane
    auto stage = [&](int t, int sel) {
        uint32_t* dst = smu + sel * KVB;
#pragma unroll
        for (int p = 0; p < 4; p++) {
            int idx = p * 128 + tid;       // 0..511
            int r = idx >> 3;              // 0..63
            int c4 = (idx & 7) * 4;        // 0..28
            uint32_t dK = (uint32_t)__cvta_generic_to_shared(dst + r * KVS + c4);
            uint32_t dV = (uint32_t)__cvta_generic_to_shared(dst + 64 * KVS + r * KVS + c4);
            cp_async16(dK, Kh + (size_t)(t * 64 + r) * 32 + c4);
            cp_async16(dV, Vh + (size_t)(t * 64 + r) * 32 + c4);
        }
        asm volatile("cp.async.commit_group;");
    };

    stage(0, 0);
    asm volatile("cp.async.wait_group 0;");
    __syncthreads();

    for (int t = 0; t < 32; t++) {
        const uint32_t Kt = smb + (t & 1) * (KVB * 4);

        // ---- QK(t) ----
        float sc[8][4];
#pragma unroll
        for (int nf = 0; nf < 8; nf++) {
#pragma unroll
            for (int i = 0; i < 4; i++) sc[nf][i] = 0.f;
#pragma unroll
            for (int kc = 0; kc < 4; kc++) {
                uint32_t b0, b1;
                ldsm_x2(b0, b1, Kt + kb_l + nf * (8 * KVS * 4) + kc * 32);
                mma_fp16(sc[nf], qa[kc], b0, b1);
            }
        }

        // ---- PV(t-1) ----
        if (t > 0) {
            const uint32_t Vp = smb + ((t - 1) & 1) * (KVB * 4) + 64 * KVS * 4;
#pragma unroll
            for (int nf = 0; nf < 8; nf++) {
                o[nf][0] *= al0; o[nf][1] *= al0;
                o[nf][2] *= al1; o[nf][3] *= al1;
            }
#pragma unroll
            for (int kc = 0; kc < 4; kc++) {
                uint32_t pa[4];
                pa[0] = Pp[ra * KVS + kc * 8 + t4];
                pa[1] = Pp[rb * KVS + kc * 8 + t4];
                pa[2] = Pp[ra * KVS + kc * 8 + 4 + t4];
                pa[3] = Pp[rb * KVS + kc * 8 + 4 + t4];
#pragma unroll
                for (int nf = 0; nf < 8; nf++) {
                    uint32_t b0, b1;
                    ldsm_x2_trans(b0, b1, Vp + vb_l + kc * (16 * KVS * 4) + nf * 16);
                    mma_fp16(o[nf], pa, b0, b1);
                }
            }
        }
        __syncthreads();

        if (t < 31) stage(t + 1, (t + 1) & 1);

        // ---- softmax(t), base-2 domain ----
        const int allones = mfl[t];
        if (!allones) {
#pragma unroll
            for (int nf = 0; nf < 8; nf++) {
                int kcol = t * 64 + nf * 8 + 2 * t4;
                int2 ma = *(const int2*)(maskg + (size_t)ra * S_ + kcol);
                int2 mb = *(const int2*)(maskg + (size_t)rb * S_ + kcol);
                if (ma.x == 0) sc[nf][0] = -1e9f;
                if (ma.y == 0) sc[nf][1] = -1e9f;
                if (mb.x == 0) sc[nf][2] = -1e9f;
                if (mb.y == 0) sc[nf][3] = -1e9f;
            }
        }
        float tma = -1e30f, tmb = -1e30f;
#pragma unroll
        for (int nf = 0; nf < 8; nf++) {
            tma = fmaxf(tma, fmaxf(sc[nf][0], sc[nf][1]));
            tmb = fmaxf(tmb, fmaxf(sc[nf][2], sc[nf][3]));
        }
        tma = fmaxf(tma, __shfl_xor_sync(0xffffffffu, tma, 1));
        tma = fmaxf(tma, __shfl_xor_sync(0xffffffffu, tma, 2));
        tmb = fmaxf(tmb, __shfl_xor_sync(0xffffffffu, tmb, 1));
        tmb = fmaxf(tmb, __shfl_xor_sync(0xffffffffu, tmb, 2));

        float mn0 = fmaxf(m0, tma);
        float mn1 = fmaxf(m1, tmb);
        al0 = ex2(m0 - mn0);
        al1 = ex2(m1 - mn1);
        m0 = mn0; m1 = mn1;

        float rs0 = 0.f, rs1 = 0.f;
#pragma unroll
        for (int nf = 0; nf < 8; nf++) {
            float p00 = ex2(sc[nf][0] - mn0);
            float p01 = ex2(sc[nf][1] - mn0);
            float p10 = ex2(sc[nf][2] - mn1);
            float p11 = ex2(sc[nf][3] - mn1);
            rs0 += p00 + p01;
            rs1 += p10 + p11;
            Pp[ra * KVS + nf * 4 + t4] = f16pk(p00, p01);
            Pp[rb * KVS + nf * 4 + t4] = f16pk(p10, p11);
        }
        rs0 += __shfl_xor_sync(0xffffffffu, rs0, 1);
        rs0 += __shfl_xor_sync(0xffffffffu, rs0, 2);
        rs1 += __shfl_xor_sync(0xffffffffu, rs1, 1);
        rs1 += __shfl_xor_sync(0xffffffffu, rs1, 2);
        l0 = l0 * al0 + rs0;
        l1 = l1 * al1 + rs1;

        if (t < 31) {
            asm volatile("cp.async.wait_group 0;");
            __syncthreads();
        }
    }

    // ---- final PV(31) ----
    __syncwarp();
    {
        const uint32_t Vp = smb + (31 & 1) * (KVB * 4) + 64 * KVS * 4;
#pragma unroll
        for (int nf = 0; nf < 8; nf++) {
            o[nf][0] *= al0; o[nf][1] *= al0;
            o[nf][2] *= al1; o[nf][3] *= al1;
        }
#pragma unroll
        for (int kc = 0; kc < 4; kc++) {
            uint32_t pa[4];
            pa[0] = Pp[ra * KVS + kc * 8 + t4];
            pa[1] = Pp[rb * KVS + kc * 8 + t4];
            pa[2] = Pp[ra * KVS + kc * 8 + 4 + t4];
            pa[3] = Pp[rb * KVS + kc * 8 + 4 + t4];
#pragma unroll
            for (int nf = 0; nf < 8; nf++) {
                uint32_t b0, b1;
                ldsm_x2_trans(b0, b1, Vp + vb_l + kc * (16 * KVS * 4) + nf * 16);
                mma_fp16(o[nf], pa, b0, b1);
            }
        }
    }

    // ---- finalize: O / l, write [B,S,D] ----
    float inv0 = 1.f / l0;
    float inv1 = 1.f / l1;
    int ga = qblk * 64 + ra;
    int gb = ga + 8;
    float* opa = out + ((size_t)b * S_ + ga) * D_ + h * 64;
    float* opb = out + ((size_t)b * S_ + gb) * D_ + h * 64;
#pragma unroll
    for (int nf = 0; nf < 8; nf++) {
        int cb = nf * 8 + 2 * t4;
        *(float2*)(opa + cb) = make_float2(o[nf][0] * inv0, o[nf][1] * inv0);
        *(float2*)(opb + cb) = make_float2(o[nf][2] * inv1, o[nf][3] * inv1);
    }
}

// ---------------------------------------------------------------------------
// Launch
// Inputs (metadata order): query, key, value, mask, Wq, bq, Wk, bk, Wv, bv
// ---------------------------------------------------------------------------
extern "C" void kernel_launch(void* const* d_in, const int* in_sizes, int n_in,
                              void* d_out, int out_size)
{
    const float* query = (const float*)d_in[0];
    const float* key   = (const float*)d_in[1];
    const float* value = (const float*)d_in[2];
    const int*   mask  = (const int*)  d_in[3];
    const float* Wq    = (const float*)d_in[4];
    const float* bq    = (const float*)d_in[5];
    const float* Wk    = (const float*)d_in[6];
    const float* bk    = (const float*)d_in[7];
    const float* Wv    = (const float*)d_in[8];
    const float* bv    = (const float*)d_in[9];
    float* out = (float*)d_out;

    // prep: fp32 -> packed fp16 planes (X and W in one launch) + mask scan
    prep_xw<<<dim3(9216, 1, 3), 256>>>(query, key, value, Wq, Wk, Wv);
    mask_scan<<<dim3(32, 8, 4), 256>>>(mask);

    // fused projections (fp16, 3-stage k64 pipeline)
    const int psmem = NSTG * STGW * (int)sizeof(uint32_t);   // 110,592 B
    cudaFuncSetAttribute(proj_gemm, cudaFuncAttributeMaxDynamicSharedMemorySize, psmem);
    proj_gemm<<<dim3(8, 64, 3), 256, psmem>>>(bq, bk, bv);

    // attention: 128 threads, 64-row q tiles, 4 CTAs/SM
    const int asmem = (2 * KVB + 64 * KVS) * (int)sizeof(uint32_t);   // 46,080 B
    cudaFuncSetAttribute(attn_mma, cudaFuncAttributeMaxDynamicSharedMemorySize, asmem);
    attn_mma<<<dim3(32, 64), 128, asmem>>>(mask, out);
}

// round 16
// speedup vs baseline: 1.2625x; 1.0095x over previous
#include <cuda_runtime.h>
#include <cuda_fp16.h>
#include <cstdint>
#include <math.h>

// Problem constants
#define B_  4
#define S_  2048
#define D_  1024
#define H_  16
#define DK_ 64

// Scratch (device globals — no allocs)
__device__ int g_mflag[B_ * 8 * 32];
// pre-converted fp16 planes (packed pairs along k: one word = 2 fp16)
__device__ uint32_t g_Xpk[(size_t)3 * 8192 * 512];
__device__ uint32_t g_Wpk[(size_t)3 * 1024 * 512];
// projected Q/K/V, packed fp16 [bh][s][32 words]; Q pre-scaled by 0.125*log2(e)
__device__ uint32_t g_Qh[(size_t)64 * 2048 * 32];
__device__ uint32_t g_Kh[(size_t)64 * 2048 * 32];
__device__ uint32_t g_Vh[(size_t)64 * 2048 * 32];

// ---------------------------------------------------------------------------
// helpers
// ---------------------------------------------------------------------------
__device__ __forceinline__ uint32_t f16pk(float x0, float x1) {
    __half2 h = __floats2half2_rn(x0, x1);
    return *(uint32_t*)&h;
}

__device__ __forceinline__ float ex2(float x) {
    float r;
    asm("ex2.approx.f32 %0, %1;" : "=f"(r) : "f"(x));
    return r;
}

__device__ __forceinline__ void mma_fp16(float* d, const uint32_t* a,
                                         uint32_t b0, uint32_t b1)
{
    asm volatile(
        "mma.sync.aligned.m16n8k16.row.col.f32.f16.f16.f32 "
        "{%0,%1,%2,%3},{%4,%5,%6,%7},{%8,%9},{%0,%1,%2,%3};"
        : "+f"(d[0]), "+f"(d[1]), "+f"(d[2]), "+f"(d[3])
        : "r"(a[0]), "r"(a[1]), "r"(a[2]), "r"(a[3]), "r"(b0), "r"(b1));
}

__device__ __forceinline__ void cp_async16(uint32_t dst_smem, const void* src) {
    asm volatile("cp.async.cg.shared.global [%0], [%1], 16;"
                 :: "r"(dst_smem), "l"(src));
}

__device__ __forceinline__ void ldsm_x4(uint32_t* r, uint32_t addr) {
    asm volatile("ldmatrix.sync.aligned.m8n8.x4.shared.b16 {%0,%1,%2,%3}, [%4];"
                 : "=r"(r[0]), "=r"(r[1]), "=r"(r[2]), "=r"(r[3]) : "r"(addr));
}

__device__ __forceinline__ void ldsm_x4_trans(uint32_t* r, uint32_t addr) {
    asm volatile("ldmatrix.sync.aligned.m8n8.x4.trans.shared.b16 {%0,%1,%2,%3}, [%4];"
                 : "=r"(r[0]), "=r"(r[1]), "=r"(r[2]), "=r"(r[3]) : "r"(addr));
}

// ---------------------------------------------------------------------------
// Prep: fp32 -> packed fp16 planes. Merged X+W in one launch.
// ---------------------------------------------------------------------------
__global__ __launch_bounds__(256)
void prep_xw(const float* __restrict__ q, const float* __restrict__ k,
             const float* __restrict__ v,
             const float* __restrict__ wq, const float* __restrict__ wk,
             const float* __restrict__ wv)
{
    const int z = blockIdx.z;
    const int x = blockIdx.x;
    const int kq = threadIdx.x;
    if (x < 8192) {
        const float* src = (z == 0) ? q : (z == 1) ? k : v;
        float4 xv = *((const float4*)(src + (size_t)x * 1024) + kq);
        size_t w = ((size_t)z * 8192 + x) * 512 + kq * 2;
        *(uint2*)&g_Xpk[w] = make_uint2(f16pk(xv.x, xv.y), f16pk(xv.z, xv.w));
    } else {
        const int n = x - 8192;
        const float* src = (z == 0) ? wq : (z == 1) ? wk : wv;
        float4 xv = *((const float4*)(src + (size_t)n * 1024) + kq);
        size_t w = ((size_t)z * 1024 + n) * 512 + kq * 2;
        *(uint2*)&g_Wpk[w] = make_uint2(f16pk(xv.x, xv.y), f16pk(xv.z, xv.w));
    }
}

// ---------------------------------------------------------------------------
// Fused projection GEMM (proven ~179us). Q scale folded with log2(e).
// ---------------------------------------------------------------------------
#define PST 36
#define PLW (128 * PST)
#define STGW (2 * PLW)
#define NSTG 3
#define QSCALE 0.1803368801f   // 0.125 * log2(e)

__global__ __launch_bounds__(256, 2)
void proj_gemm(const float* __restrict__ bq, const float* __restrict__ bk,
               const float* __restrict__ bv)
{
    extern __shared__ uint32_t sbuf[];

    const int tid  = threadIdx.x;
    const int warp = tid >> 5;
    const int lane = tid & 31;
    const int grp  = lane >> 2;
    const int t4   = lane & 3;
    const int bm   = blockIdx.y;
    const int bn   = blockIdx.x;
    const int z    = blockIdx.z;
    const int wm   = (warp >> 2) * 64;
    const int wn   = (warp & 3) * 32;

    const float* bias = (z == 0) ? bq : (z == 1) ? bk : bv;
    uint32_t* outh    = (z == 0) ? g_Qh : (z == 1) ? g_Kh : g_Vh;
    const bool scale  = (z == 0);

    const uint32_t* xpk = g_Xpk + ((size_t)z * 8192 + bm * 128) * 512;
    const uint32_t* wpk = g_Wpk + ((size_t)z * 1024 + bn * 128) * 512;

    auto issue = [&](int kt, int sel) {
        uint32_t* dst = sbuf + sel * STGW;
#pragma unroll
        for (int q = 0; q < 4; q++) {
            int idx = q * 256 + tid;
            int r = idx >> 3;
            int g4 = (idx & 7) * 4;
            uint32_t dA = (uint32_t)__cvta_generic_to_shared(dst + r * PST + g4);
            uint32_t dB = (uint32_t)__cvta_generic_to_shared(dst + PLW + r * PST + g4);
            cp_async16(dA, xpk + (size_t)r * 512 + kt * 32 + g4);
            cp_async16(dB, wpk + (size_t)r * 512 + kt * 32 + g4);
        }
        asm volatile("cp.async.commit_group;");
    };

    float acc[4][4][4];
#pragma unroll
    for (int mf = 0; mf < 4; mf++)
#pragma unroll
        for (int nf = 0; nf < 4; nf++)
#pragma unroll
            for (int i = 0; i < 4; i++) acc[mf][nf][i] = 0.f;

    issue(0, 0);
    issue(1, 1);

    int s_cur = 0;
    int s_nxt = 2;
    for (int ks = 0; ks < 16; ks++) {
        asm volatile("cp.async.wait_group 1;");
        __syncthreads();

        if (ks + 2 < 16) issue(ks + 2, s_nxt);

        const uint32_t* sA = sbuf + s_cur * STGW;
        const uint32_t* sB = sA + PLW;

#pragma unroll
        for (int kc = 0; kc < 4; kc++) {
            const int kp = kc * 8 + t4;
            uint32_t ah[4][4];
#pragma unroll
            for (int mf = 0; mf < 4; mf++) {
                int r0 = wm + mf * 16 + grp;
                ah[mf][0] = sA[r0 * PST + kp];
                ah[mf][1] = sA[(r0 + 8) * PST + kp];
                ah[mf][2] = sA[r0 * PST + kp + 4];
                ah[mf][3] = sA[(r0 + 8) * PST + kp + 4];
            }
#pragma unroll
            for (int nf = 0; nf < 4; nf++) {
                int n = wn + nf * 8 + grp;
                uint32_t b0 = sB[n * PST + kp];
                uint32_t b1 = sB[n * PST + kp + 4];
#pragma unroll
                for (int mf = 0; mf < 4; mf++)
                    mma_fp16(acc[mf][nf], ah[mf], b0, b1);
            }
        }

        s_cur = (s_cur + 1 == NSTG) ? 0 : s_cur + 1;
        s_nxt = (s_nxt + 1 == NSTG) ? 0 : s_nxt + 1;
    }

#pragma unroll
    for (int mf = 0; mf < 4; mf++) {
        int row0 = bm * 128 + wm + mf * 16 + grp;
        int row1 = row0 + 8;
        int b0i = row0 >> 11, s0 = row0 & 2047;
        int b1i = row1 >> 11, s1 = row1 & 2047;
#pragma unroll
        for (int nf = 0; nf < 4; nf++) {
            int col = bn * 128 + wn + nf * 8 + 2 * t4;
            int h  = col >> 6;
            int wi = (col & 63) >> 1;
            float bb0 = bias[col], bb1 = bias[col + 1];
            float v00 = acc[mf][nf][0] + bb0;
            float v01 = acc[mf][nf][1] + bb1;
            float v10 = acc[mf][nf][2] + bb0;
            float v11 = acc[mf][nf][3] + bb1;
            if (scale) { v00 *= QSCALE; v01 *= QSCALE; v10 *= QSCALE; v11 *= QSCALE; }
            outh[((size_t)(b0i * 16 + h) * 2048 + s0) * 32 + wi] = f16pk(v00, v01);
            outh[((size_t)(b1i * 16 + h) * 2048 + s1) * 32 + wi] = f16pk(v10, v11);
        }
    }
}

// ---------------------------------------------------------------------------
// Mask scan — coalesced (proven)
// ---------------------------------------------------------------------------
__global__ void mask_scan(const int* __restrict__ mask)
{
    const int kt = blockIdx.x;
    const int qt = blockIdx.y;
    const int b  = blockIdx.z;
    const int tr = threadIdx.x >> 4;
    const int tc = (threadIdx.x & 15) * 4;
    int ok = 1;
#pragma unroll
    for (int p = 0; p < 16; p++) {
        int row = p * 16 + tr;
        int4 v = *(const int4*)(mask + ((size_t)b * S_ + qt * 256 + row) * S_ + kt * 64 + tc);
        ok &= (v.x != 0) & (v.y != 0) & (v.z != 0) & (v.w != 0);
    }
    ok = __syncthreads_and(ok);
    if (threadIdx.x == 0) g_mflag[(b * 8 + qt) * 32 + kt] = ok;
}

// ---------------------------------------------------------------------------
// Flash attention, FP16, deferred-PV, base-2 softmax, 4 CTAs/SM.
// Round 16: P kept in REGISTERS (QK C-fragment == PV A-fragment layout) —
// no P smem round-trip; K/V B-fragments via ldmatrix.x4 (nf-pairs).
// smem: 2 KV buffers only = 36,864 B per CTA.
// ---------------------------------------------------------------------------
#define KVS 36
#define KVB (2 * 64 * KVS)     // words per KV buffer (K then V)

__global__ __launch_bounds__(128, 4)
void attn_mma(const int* __restrict__ mask, float* __restrict__ out)
{
    extern __shared__ uint32_t smu[];

    const int tid  = threadIdx.x;
    const int warp = tid >> 5;     // 0..3
    const int lane = tid & 31;
    const int grp  = lane >> 2;
    const int t4   = lane & 3;

    const int qblk = blockIdx.x;   // 0..31 (64-row q tiles)
    const int bh   = blockIdx.y;   // 0..63
    const int b    = bh >> 4;
    const int h    = bh & 15;

    const uint32_t* Qh = g_Qh + ((size_t)bh * 2048 + qblk * 64) * 32;
    const uint32_t* Kh = g_Kh + (size_t)bh * 2048 * 32;
    const uint32_t* Vh = g_Vh + (size_t)bh * 2048 * 32;
    const int* maskg = mask + (size_t)b * S_ * S_ + (size_t)(qblk * 64) * S_;
    const int* mfl = g_mflag + (b * 8 + (qblk >> 2)) * 32;

    const int ra = warp * 16 + grp;   // 0..63
    const int rb = ra + 8;

    const uint32_t smb = (uint32_t)__cvta_generic_to_shared(smu);
    // ldmatrix.x4 per-lane bases (bytes)
    //  K (non-trans): lanes -> rows nf2*16 + (lane>>4)*8 + (lane&7), col sel bit3
    const uint32_t kx4_l = (((lane >> 4) * 8 + (lane & 7)) * (KVS * 4))
                         + (((lane >> 3) & 1) * 16);
    //  V (trans): lanes -> k rows kc*16 + (lane&15), col group lane>>4
    const uint32_t vx4_l = ((lane & 15) * (KVS * 4)) + ((lane >> 4) * 16);

    // ---- Q fragments: direct LDG (one time) ----
    uint32_t qa[4][4];
#pragma unroll
    for (int kc = 0; kc < 4; kc++) {
        qa[kc][0] = Qh[(size_t)ra * 32 + kc * 8 + t4];
        qa[kc][1] = Qh[(size_t)rb * 32 + kc * 8 + t4];
        qa[kc][2] = Qh[(size_t)ra * 32 + kc * 8 + 4 + t4];
        qa[kc][3] = Qh[(size_t)rb * 32 + kc * 8 + 4 + t4];
    }

    float o[8][4];
#pragma unroll
    for (int nf = 0; nf < 8; nf++)
#pragma unroll
        for (int i = 0; i < 4; i++) o[nf][i] = 0.f;

    uint32_t pp[4][4];   // P(t-1) A-fragments, register-resident
    float m0 = -1e30f, m1 = -1e30f, l0 = 0.f, l1 = 0.f;
    float al0 = 1.f, al1 = 1.f;

    auto stage = [&](int t, int sel) {
        uint32_t* dst = smu + sel * KVB;
#pragma unroll
        for (int p = 0; p < 4; p++) {
            int idx = p * 128 + tid;       // 0..511
            int r = idx >> 3;              // 0..63
            int c4 = (idx & 7) * 4;        // 0..28
            uint32_t dK = (uint32_t)__cvta_generic_to_shared(dst + r * KVS + c4);
            uint32_t dV = (uint32_t)__cvta_generic_to_shared(dst + 64 * KVS + r * KVS + c4);
            cp_async16(dK, Kh + (size_t)(t * 64 + r) * 32 + c4);
            cp_async16(dV, Vh + (size_t)(t * 64 + r) * 32 + c4);
        }
        asm volatile("cp.async.commit_group;");
    };

    stage(0, 0);
    asm volatile("cp.async.wait_group 0;");
    __syncthreads();

    for (int t = 0; t < 32; t++) {
        const uint32_t Kt = smb + (t & 1) * (KVB * 4);

        // ---- QK(t): B-frags via ldmatrix.x4 (nf pairs) ----
        float sc[8][4];
#pragma unroll
        for (int nf = 0; nf < 8; nf++)
#pragma unroll
            for (int i = 0; i < 4; i++) sc[nf][i] = 0.f;
#pragma unroll
        for (int nf2 = 0; nf2 < 4; nf2++) {
#pragma unroll
            for (int kc = 0; kc < 4; kc++) {
                uint32_t bb[4];
                ldsm_x4(bb, Kt + kx4_l + nf2 * (16 * KVS * 4) + kc * 32);
                mma_fp16(sc[2 * nf2],     qa[kc], bb[0], bb[1]);
                mma_fp16(sc[2 * nf2 + 1], qa[kc], bb[2], bb[3]);
            }
        }

        // ---- PV(t-1): P from registers (pp), V via ldmatrix.x4.trans ----
        if (t > 0) {
            const uint32_t Vp = smb + ((t - 1) & 1) * (KVB * 4) + 64 * KVS * 4;
#pragma unroll
            for (int nf = 0; nf < 8; nf++) {
                o[nf][0] *= al0; o[nf][1] *= al0;
                o[nf][2] *= al1; o[nf][3] *= al1;
            }
#pragma unroll
            for (int kc = 0; kc < 4; kc++) {
#pragma unroll
                for (int nf2 = 0; nf2 < 4; nf2++) {
                    uint32_t bb[4];
                    ldsm_x4_trans(bb, Vp + vx4_l + kc * (16 * KVS * 4) + nf2 * 32);
                    mma_fp16(o[2 * nf2],     pp[kc], bb[0], bb[1]);
                    mma_fp16(o[2 * nf2 + 1], pp[kc], bb[2], bb[3]);
                }
            }
        }
        __syncthreads();   // V buffer (t-1)&1 fully consumed

        if (t < 31) stage(t + 1, (t + 1) & 1);

        // ---- softmax(t), base-2; pack P(t) into pp regs ----
        const int allones = mfl[t];
        if (!allones) {
#pragma unroll
            for (int nf = 0; nf < 8; nf++) {
                int kcol = t * 64 + nf * 8 + 2 * t4;
                int2 ma = *(const int2*)(maskg + (size_t)ra * S_ + kcol);
                int2 mb = *(const int2*)(maskg + (size_t)rb * S_ + kcol);
                if (ma.x == 0) sc[nf][0] = -1e9f;
                if (ma.y == 0) sc[nf][1] = -1e9f;
                if (mb.x == 0) sc[nf][2] = -1e9f;
                if (mb.y == 0) sc[nf][3] = -1e9f;
            }
        }
        float tma = -1e30f, tmb = -1e30f;
#pragma unroll
        for (int nf = 0; nf < 8; nf++) {
            tma = fmaxf(tma, fmaxf(sc[nf][0], sc[nf][1]));
            tmb = fmaxf(tmb, fmaxf(sc[nf][2], sc[nf][3]));
        }
        tma = fmaxf(tma, __shfl_xor_sync(0xffffffffu, tma, 1));
        tma = fmaxf(tma, __shfl_xor_sync(0xffffffffu, tma, 2));
        tmb = fmaxf(tmb, __shfl_xor_sync(0xffffffffu, tmb, 1));
        tmb = fmaxf(tmb, __shfl_xor_sync(0xffffffffu, tmb, 2));

        float mn0 = fmaxf(m0, tma);
        float mn1 = fmaxf(m1, tmb);
        al0 = ex2(m0 - mn0);
        al1 = ex2(m1 - mn1);
        m0 = mn0; m1 = mn1;

        float rs0 = 0.f, rs1 = 0.f;
#pragma unroll
        for (int nf = 0; nf < 8; nf++) {
            float p00 = ex2(sc[nf][0] - mn0);
            float p01 = ex2(sc[nf][1] - mn0);
            float p10 = ex2(sc[nf][2] - mn1);
            float p11 = ex2(sc[nf][3] - mn1);
            rs0 += p00 + p01;
            rs1 += p10 + p11;
            const int kc = nf >> 1;
            if ((nf & 1) == 0) {
                pp[kc][0] = f16pk(p00, p01);   // row ra, k-lo half
                pp[kc][1] = f16pk(p10, p11);   // row rb, k-lo half
            } else {
                pp[kc][2] = f16pk(p00, p01);   // row ra, k-hi half
                pp[kc][3] = f16pk(p10, p11);   // row rb, k-hi half
            }
        }
        rs0 += __shfl_xor_sync(0xffffffffu, rs0, 1);
        rs0 += __shfl_xor_sync(0xffffffffu, rs0, 2);
        rs1 += __shfl_xor_sync(0xffffffffu, rs1, 1);
        rs1 += __shfl_xor_sync(0xffffffffu, rs1, 2);
        l0 = l0 * al0 + rs0;
        l1 = l1 * al1 + rs1;

        if (t < 31) {
            asm volatile("cp.async.wait_group 0;");
            __syncthreads();   // KV(t+1) visible
        }
    }

    // ---- final PV(31): pp from softmax(31), V in buffer 1 ----
    {
        const uint32_t Vp = smb + (31 & 1) * (KVB * 4) + 64 * KVS * 4;
#pragma unroll
        for (int nf = 0; nf < 8; nf++) {
            o[nf][0] *= al0; o[nf][1] *= al0;
            o[nf][2] *= al1; o[nf][3] *= al1;
        }
#pragma unroll
        for (int kc = 0; kc < 4; kc++) {
#pragma unroll
            for (int nf2 = 0; nf2 < 4; nf2++) {
                uint32_t bb[4];
                ldsm_x4_trans(bb, Vp + vx4_l + kc * (16 * KVS * 4) + nf2 * 32);
                mma_fp16(o[2 * nf2],     pp[kc], bb[0], bb[1]);
                mma_fp16(o[2 * nf2 + 1], pp[kc], bb[2], bb[3]);
            }
        }
    }

    // ---- finalize: O / l, write [B,S,D] ----
    float inv0 = 1.f / l0;
    float inv1 = 1.f / l1;
    int ga = qblk * 64 + ra;
    int gb = ga + 8;
    float* opa = out + ((size_t)b * S_ + ga) * D_ + h * 64;
    float* opb = out + ((size_t)b * S_ + gb) * D_ + h * 64;
#pragma unroll
    for (int nf = 0; nf < 8; nf++) {
        int cb = nf * 8 + 2 * t4;
        *(float2*)(opa + cb) = make_float2(o[nf][0] * inv0, o[nf][1] * inv0);
        *(float2*)(opb + cb) = make_float2(o[nf][2] * inv1, o[nf][3] * inv1);
    }
}

// ---------------------------------------------------------------------------
// Launch
// Inputs (metadata order): query, key, value, mask, Wq, bq, Wk, bk, Wv, bv
// ---------------------------------------------------------------------------
extern "C" void kernel_launch(void* const* d_in, const int* in_sizes, int n_in,
                              void* d_out, int out_size)
{
    const float* query = (const float*)d_in[0];
    const float* key   = (const float*)d_in[1];
    const float* value = (const float*)d_in[2];
    const int*   mask  = (const int*)  d_in[3];
    const float* Wq    = (const float*)d_in[4];
    const float* bq    = (const float*)d_in[5];
    const float* Wk    = (const float*)d_in[6];
    const float* bk    = (const float*)d_in[7];
    const float* Wv    = (const float*)d_in[8];
    const float* bv    = (const float*)d_in[9];
    float* out = (float*)d_out;

    // prep: fp32 -> packed fp16 planes (X and W in one launch) + mask scan
    prep_xw<<<dim3(9216, 1, 3), 256>>>(query, key, value, Wq, Wk, Wv);
    mask_scan<<<dim3(32, 8, 4), 256>>>(mask);

    // fused projections (fp16, 3-stage k64 pipeline)
    const int psmem = NSTG * STGW * (int)sizeof(uint32_t);   // 110,592 B
    cudaFuncSetAttribute(proj_gemm, cudaFuncAttributeMaxDynamicSharedMemorySize, psmem);
    proj_gemm<<<dim3(8, 64, 3), 256, psmem>>>(bq, bk, bv);

    // attention: 128 threads, 64-row q tiles, 4 CTAs/SM, register-resident P
    const int asmem = 2 * KVB * (int)sizeof(uint32_t);   // 36,864 B
    cudaFuncSetAttribute(attn_mma, cudaFuncAttributeMaxDynamicSharedMemorySize, asmem);
    attn_mma<<<dim3(32, 64), 128, asmem>>>(mask, out);
}